// round 14
// baseline (speedup 1.0000x reference)
#include <cuda_runtime.h>
#include <cuda_fp16.h>
#include <cstdint>

// ============================================================================
// EdgeTransformerLayer (B=2, N=64, D=256, H=8, DK=32, DFF=1024)
// GEMMs: mma.sync.m16n8k16 fp16; TM=128 tiles for proj/ffn1, TM=64 tiles for
// wo/ffn2 (256 CTAs -> all SMs busy). Attention: TX=8, y-split x4 (16 rows,
// 64 thr, 512 CTAs), rk/rv fp16 streams, f32x2 math.
// ============================================================================

namespace {
constexpr int Bb  = 2;
constexpr int Nn  = 64;
constexpr int Dd  = 256;
constexpr int Hh  = 8;
constexpr int DKk = 32;
constexpr int DFF = 1024;
constexpr int RR  = Bb * Nn * Nn;   // 8192
constexpr int SPH = 40;             // GEMM smem row stride (halfs): 80B
constexpr int TX  = 8;              // attention x-tile per CTA
}

// ---- device-global scratch (no allocation allowed) --------------------------
__device__ float  g_h     [RR * Dd];
__device__ __half g_hh    [RR * Dd];
__device__ float  g_proj  [RR * DFF];  // [0,256)=lk*scale [256,512)=rk [512,768)=lv [768,1024)=rv
__device__ __half g_projh [RR * DFF];  // fp16 shadow (rk/rv cols valid)
__device__ __half g_att   [RR * Dd];
__device__ float  g_hres  [RR * Dd];
__device__ float  g_h2    [RR * Dd];
__device__ __half g_h2h   [RR * Dd];
__device__ __half g_ffn   [RR * DFF];
__device__ __half g_Wh_qkv[DFF * Dd];
__device__ __half g_Wh_o  [Dd * Dd];
__device__ __half g_Wh_1  [DFF * Dd];
__device__ __half g_Wh_2  [Dd * DFF];
__device__ unsigned char g_maskT[Bb * Nn * Nn * Nn];  // [b][a][y][x]

// ============================================================================
// helpers
// ============================================================================
__device__ __forceinline__ uint32_t smem_u32(const void* p) {
    uint32_t a;
    asm("{ .reg .u64 t; cvta.to.shared.u64 t, %1; cvt.u32.u64 %0, t; }" : "=r"(a) : "l"(p));
    return a;
}

__device__ __forceinline__ void mma_f16(float c[4],
                                        uint32_t a0, uint32_t a1, uint32_t a2, uint32_t a3,
                                        uint32_t b0, uint32_t b1) {
    asm volatile(
        "mma.sync.aligned.m16n8k16.row.col.f32.f16.f16.f32 "
        "{%0,%1,%2,%3}, {%4,%5,%6,%7}, {%8,%9}, {%0,%1,%2,%3};"
        : "+f"(c[0]), "+f"(c[1]), "+f"(c[2]), "+f"(c[3])
        : "r"(a0), "r"(a1), "r"(a2), "r"(a3), "r"(b0), "r"(b1));
}

__device__ __forceinline__ void ldsm_x4(uint32_t r[4], uint32_t addr) {
    asm volatile("ldmatrix.sync.aligned.m8n8.x4.shared.b16 {%0,%1,%2,%3}, [%4];"
                 : "=r"(r[0]), "=r"(r[1]), "=r"(r[2]), "=r"(r[3]) : "r"(addr));
}
__device__ __forceinline__ void ldsm_x2(uint32_t r[2], uint32_t addr) {
    asm volatile("ldmatrix.sync.aligned.m8n8.x2.shared.b16 {%0,%1}, [%2];"
                 : "=r"(r[0]), "=r"(r[1]) : "r"(addr));
}

__device__ __forceinline__ uint32_t h2u(__half2 h) {
    uint32_t u; asm("mov.b32 %0, %1;" : "=r"(u) : "r"(*(uint32_t*)&h)); return u;
}

// ---- packed f32x2 ------------------------------------------------------------
typedef unsigned long long u64;
__device__ __forceinline__ u64 pk2(float lo, float hi) {
    u64 r; asm("mov.b64 %0, {%1,%2};" : "=l"(r) : "f"(lo), "f"(hi)); return r;
}
__device__ __forceinline__ void upk2(u64 v, float& lo, float& hi) {
    asm("mov.b64 {%0,%1}, %2;" : "=f"(lo), "=f"(hi) : "l"(v));
}
__device__ __forceinline__ u64 mul2(u64 a, u64 b) {
    u64 d; asm("mul.rn.f32x2 %0, %1, %2;" : "=l"(d) : "l"(a), "l"(b)); return d;
}
__device__ __forceinline__ u64 fma2(u64 a, u64 b, u64 c) {
    u64 d; asm("fma.rn.f32x2 %0, %1, %2, %3;" : "=l"(d) : "l"(a), "l"(b), "l"(c)); return d;
}

__device__ __forceinline__ void h8_to_f32x2(uint4 h, u64& a0, u64& a1, u64& b0, u64& b1) {
    const float2 f0 = __half22float2(*(__half2*)&h.x);
    const float2 f1 = __half22float2(*(__half2*)&h.y);
    const float2 f2 = __half22float2(*(__half2*)&h.z);
    const float2 f3 = __half22float2(*(__half2*)&h.w);
    a0 = pk2(f0.x, f0.y); a1 = pk2(f1.x, f1.y);
    b0 = pk2(f2.x, f2.y); b1 = pk2(f3.x, f3.y);
}

// ============================================================================
// prep: weight transpose -> [N,K] fp16 (Wlk pre-scaled) + mask transpose
// ============================================================================
__device__ __forceinline__ __half* trh_dst(int which) {
    switch (which) {
        case 0: return g_Wh_qkv;
        case 1: return g_Wh_qkv + 256 * 256;
        case 2: return g_Wh_qkv + 512 * 256;
        case 3: return g_Wh_qkv + 768 * 256;
        case 4: return g_Wh_o;
        case 5: return g_Wh_1;
        default: return g_Wh_2;
    }
}

__global__ __launch_bounds__(256) void k_prep(const float* __restrict__ Wlk,
                                              const float* __restrict__ Wrk,
                                              const float* __restrict__ Wlv,
                                              const float* __restrict__ Wrv,
                                              const float* __restrict__ Wo,
                                              const float* __restrict__ W1,
                                              const float* __restrict__ W2,
                                              const unsigned char* __restrict__ mask)
{
    const int id = blockIdx.x;
    if (id >= 832) {
        const int g = (id - 832) * 256 + threadIdx.x;
        const int x  = g & 63;
        const int yy = (g >> 6) & 63;
        const int a  = (g >> 12) & 63;
        const int bb = g >> 18;
        g_maskT[g] = mask[(((bb * 64 + x) * 64 + a) * 64) + yy];
        return;
    }

    __shared__ float tile[32][33];
    const float* src;
    __half* dst;
    float scale = 1.0f;
    int K, N, n0, k0;
    if (id < 320) {
        const int w = id >> 6;
        const int tl = id & 63;
        src = (w == 0) ? Wlk : (w == 1) ? Wrk : (w == 2) ? Wlv : (w == 3) ? Wrv : Wo;
        dst = trh_dst(w);
        if (w == 0) scale = 0.17677669529663687f;   // 1/sqrt(32)
        K = 256; N = 256;
        n0 = (tl & 7) * 32; k0 = (tl >> 3) * 32;
    } else if (id < 576) {
        const int tl = id - 320;
        src = W1; dst = g_Wh_1; K = 256; N = 1024;
        n0 = (tl & 31) * 32; k0 = (tl >> 5) * 32;
    } else {
        const int tl = id - 576;
        src = W2; dst = g_Wh_2; K = 1024; N = 256;
        n0 = (tl & 7) * 32; k0 = (tl >> 3) * 32;
    }
    const int tx = threadIdx.x & 31;
    const int ty = threadIdx.x >> 5;
#pragma unroll
    for (int r = ty; r < 32; r += 8)
        tile[r][tx] = src[(size_t)(k0 + r) * N + n0 + tx];
    __syncthreads();
#pragma unroll
    for (int r = ty; r < 32; r += 8)
        dst[(size_t)(n0 + r) * K + k0 + tx] = __float2half_rn(tile[tx][r] * scale);
}

// ============================================================================
// LayerNorm: warp per row; fp32 + fp16 outputs
// ============================================================================
__device__ __forceinline__ void ln_body(const float* __restrict__ in,
                                        const float* __restrict__ gam,
                                        const float* __restrict__ bet,
                                        float* __restrict__ out,
                                        __half* __restrict__ outh)
{
    const int row  = blockIdx.x * 8 + (threadIdx.x >> 5);
    const int lane = threadIdx.x & 31;
    const float* rp = in + (size_t)row * Dd + lane * 8;
    const float4 v0 = *(const float4*)rp;
    const float4 v1 = *(const float4*)(rp + 4);
    float s  = v0.x + v0.y + v0.z + v0.w + v1.x + v1.y + v1.z + v1.w;
    float s2 = v0.x*v0.x + v0.y*v0.y + v0.z*v0.z + v0.w*v0.w
             + v1.x*v1.x + v1.y*v1.y + v1.z*v1.z + v1.w*v1.w;
#pragma unroll
    for (int o = 16; o; o >>= 1) {
        s  += __shfl_xor_sync(0xffffffffu, s,  o);
        s2 += __shfl_xor_sync(0xffffffffu, s2, o);
    }
    const float mean = s * (1.0f / Dd);
    const float var  = s2 * (1.0f / Dd) - mean * mean;
    const float inv  = rsqrtf(var + 1e-5f);
    const float4 g0 = *(const float4*)(gam + lane * 8);
    const float4 g1 = *(const float4*)(gam + lane * 8 + 4);
    const float4 b0 = *(const float4*)(bet + lane * 8);
    const float4 b1 = *(const float4*)(bet + lane * 8 + 4);
    float4 o0, o1;
    o0.x = (v0.x - mean) * inv * g0.x + b0.x;
    o0.y = (v0.y - mean) * inv * g0.y + b0.y;
    o0.z = (v0.z - mean) * inv * g0.z + b0.z;
    o0.w = (v0.w - mean) * inv * g0.w + b0.w;
    o1.x = (v1.x - mean) * inv * g1.x + b1.x;
    o1.y = (v1.y - mean) * inv * g1.y + b1.y;
    o1.z = (v1.z - mean) * inv * g1.z + b1.z;
    o1.w = (v1.w - mean) * inv * g1.w + b1.w;
    float* op = out + (size_t)row * Dd + lane * 8;
    *(float4*)op       = o0;
    *(float4*)(op + 4) = o1;
    uint4 hv;
    hv.x = h2u(__floats2half2_rn(o0.x, o0.y));
    hv.y = h2u(__floats2half2_rn(o0.z, o0.w));
    hv.z = h2u(__floats2half2_rn(o1.x, o1.y));
    hv.w = h2u(__floats2half2_rn(o1.z, o1.w));
    *(uint4*)(outh + (size_t)row * Dd + lane * 8) = hv;
}

__global__ __launch_bounds__(256) void ln1_kernel(const float* __restrict__ x,
                                                  const float* __restrict__ g1,
                                                  const float* __restrict__ be1)
{ ln_body(x, g1, be1, g_h, g_hh); }

__global__ __launch_bounds__(256) void ln2_kernel(const float* __restrict__ g2,
                                                  const float* __restrict__ be2)
{ ln_body(g_hres, g2, be2, g_h2, g_h2h); }

// ============================================================================
// fp16 mma GEMM, TM x 128 CTA tile (TM in {128, 64}).
// TM=128: 8 warps 2x4, warp tile 64x32. TM=64: 8 warps 1x8, warp tile 64x16.
// EPI: 0 proj (f32 + fp16 shadow for rk/rv tiles); 1 +Cadd f32;
//      3 +bias+Cadd f32; 4 +bias,relu -> fp16.
// ============================================================================
template <int TM, int K, int NC, int EPI>
__device__ __forceinline__ void gemm_hh(const __half* __restrict__ A,
                                        const __half* __restrict__ Wh,
                                        const float* __restrict__ Cadd,
                                        const float* __restrict__ bias,
                                        void* __restrict__ Cout)
{
    constexpr int NCH = K / 32;
    constexpr int ABUF = TM * SPH;
    constexpr int BBUF = 128 * SPH;
    constexpr int NIN  = (TM == 128) ? 4 : 2;   // n8 tiles per warp
    __shared__ __half As[2][ABUF];
    __shared__ __half Bs[2][BBUF];

    const int t    = threadIdx.x;
    const int lane = t & 31;
    const int wid  = t >> 5;
    const int gr   = lane >> 2;
    const int tig  = lane & 3;
    const int wm   = (TM == 128) ? (wid & 1) * 64 : 0;
    const int wn   = (TM == 128) ? (wid >> 1) * 32 : wid * 16;

    const int bm = blockIdx.y * TM;
    const int bn = blockIdx.x * 128;

    const uint32_t a_base = smem_u32(As) +
        ((wm + (lane & 15)) * SPH + ((lane >> 4) & 1) * 8) * 2;
    const uint32_t b_base = smem_u32(Bs) +
        ((wn + (lane & 7)) * SPH + ((lane >> 3) & 1) * 8) * 2;

    // A loader geometry
    const int lrowA = (TM == 128) ? (t >> 1) : (t >> 2);
    const int lkoA  = (TM == 128) ? (t & 1) * 16 : (t & 3) * 8;
    const int giA   = (TM == 128) ? (t & 1) * 2 : (t & 3);
    // B loader geometry (always 128 rows x 2 uint4/thread)
    const int lrowB = t >> 1;
    const int lkoB  = (t & 1) * 16;
    const int giB   = (t & 1) * 2;

    const uint4* Agh = (const uint4*)(A  + (size_t)(bm + lrowA) * K);
    const uint4* Bgh = (const uint4*)(Wh + (size_t)(bn + lrowB) * K);

    uint4 pa0, pa1, pb0, pb1;
    pa0 = Agh[giA];
    if (TM == 128) pa1 = Agh[giA + 1];
    pb0 = Bgh[giB];
    pb1 = Bgh[giB + 1];

    float acc[4][NIN][4];
#pragma unroll
    for (int im = 0; im < 4; im++)
#pragma unroll
        for (int in = 0; in < NIN; in++)
#pragma unroll
            for (int j = 0; j < 4; j++) acc[im][in][j] = 0.f;

    {
        __half* asw = &As[0][lrowA * SPH + lkoA];
        *(uint4*)asw = pa0;
        if (TM == 128) *(uint4*)(asw + 8) = pa1;
        __half* bsw = &Bs[0][lrowB * SPH + lkoB];
        *(uint4*)bsw       = pb0;
        *(uint4*)(bsw + 8) = pb1;
    }
    __syncthreads();

    for (int c = 0; c < NCH; c++) {
        const int buf = c & 1;

        if (c + 1 < NCH) {
            pa0 = Agh[giA + (c + 1) * 4];
            if (TM == 128) pa1 = Agh[giA + (c + 1) * 4 + 1];
            pb0 = Bgh[giB + (c + 1) * 4];
            pb1 = Bgh[giB + (c + 1) * 4 + 1];
        }

        const uint32_t a_addr = a_base + (uint32_t)(buf * ABUF * 2);
        const uint32_t b_addr = b_base + (uint32_t)(buf * BBUF * 2);
#pragma unroll
        for (int ks = 0; ks < 2; ks++) {
            uint32_t af[4][4], bf[NIN][2];
#pragma unroll
            for (int im = 0; im < 4; im++)
                ldsm_x4(af[im], a_addr + (uint32_t)(im * 16 * SPH * 2 + ks * 32));
#pragma unroll
            for (int in = 0; in < NIN; in++)
                ldsm_x2(bf[in], b_addr + (uint32_t)(in * 8 * SPH * 2 + ks * 32));
#pragma unroll
            for (int im = 0; im < 4; im++)
#pragma unroll
                for (int in = 0; in < NIN; in++)
                    mma_f16(acc[im][in], af[im][0], af[im][1], af[im][2], af[im][3],
                            bf[in][0], bf[in][1]);
        }

        if (c + 1 < NCH) {
            const int nb = buf ^ 1;
            __half* asw = &As[nb][lrowA * SPH + lkoA];
            *(uint4*)asw = pa0;
            if (TM == 128) *(uint4*)(asw + 8) = pa1;
            __half* bsw = &Bs[nb][lrowB * SPH + lkoB];
            *(uint4*)bsw       = pb0;
            *(uint4*)(bsw + 8) = pb1;
            __syncthreads();
        }
    }

    // epilogue
    const bool shadow = (EPI == 0) && ((bn >= 256 && bn < 512) || bn >= 768);
#pragma unroll
    for (int im = 0; im < 4; im++) {
        const int r0 = bm + wm + im * 16 + gr;
#pragma unroll
        for (int in = 0; in < NIN; in++) {
            const int col = bn + wn + in * 8 + 2 * tig;
            float2 v0 = make_float2(acc[im][in][0], acc[im][in][1]);
            float2 v1 = make_float2(acc[im][in][2], acc[im][in][3]);
            if (EPI == 3 || EPI == 4) {
                const float2 bb = *(const float2*)&bias[col];
                v0.x += bb.x; v0.y += bb.y;
                v1.x += bb.x; v1.y += bb.y;
            }
            if (EPI == 4) {
                v0.x = fmaxf(v0.x, 0.f); v0.y = fmaxf(v0.y, 0.f);
                v1.x = fmaxf(v1.x, 0.f); v1.y = fmaxf(v1.y, 0.f);
            }
            if (EPI == 1 || EPI == 3) {
                const float2 c0 = *(const float2*)&Cadd[(size_t)r0 * NC + col];
                const float2 c1 = *(const float2*)&Cadd[(size_t)(r0 + 8) * NC + col];
                v0.x += c0.x; v0.y += c0.y;
                v1.x += c1.x; v1.y += c1.y;
            }
            if (EPI == 4) {
                __half* Ch = (__half*)Cout;
                *(uint32_t*)&Ch[(size_t)r0 * NC + col] =
                    h2u(__floats2half2_rn(v0.x, v0.y));
                *(uint32_t*)&Ch[(size_t)(r0 + 8) * NC + col] =
                    h2u(__floats2half2_rn(v1.x, v1.y));
            } else {
                float* Cf = (float*)Cout;
                *(float2*)&Cf[(size_t)r0 * NC + col]       = v0;
                *(float2*)&Cf[(size_t)(r0 + 8) * NC + col] = v1;
                if (shadow) {
                    *(uint32_t*)&g_projh[(size_t)r0 * NC + col] =
                        h2u(__floats2half2_rn(v0.x, v0.y));
                    *(uint32_t*)&g_projh[(size_t)(r0 + 8) * NC + col] =
                        h2u(__floats2half2_rn(v1.x, v1.y));
                }
            }
        }
    }
}

__global__ __launch_bounds__(256, 2) void k_proj_tc()
{ gemm_hh<128, Dd, DFF, 0>(g_hh, g_Wh_qkv, nullptr, nullptr, g_proj); }

__global__ __launch_bounds__(256, 3) void k_wo_tc()
{ gemm_hh<64, Dd, Dd, 1>(g_att, g_Wh_o, g_h, nullptr, g_hres); }

__global__ __launch_bounds__(256, 2) void k_ffn1_tc(const float* __restrict__ b1)
{ gemm_hh<128, Dd, DFF, 4>(g_h2h, g_Wh_1, nullptr, b1, g_ffn); }

__global__ __launch_bounds__(256, 3) void k_ffn2_tc(const float* __restrict__ b2,
                                                    float* __restrict__ out)
{ gemm_hh<64, DFF, Dd, 3>(g_ffn, g_Wh_2, g_h2, b2, out); }

// ============================================================================
// Triangle attention v11 — TX=8, y-split x4: 16 y-rows/CTA, 64 threads,
// grid (32, 8, 2) = 512 CTAs. rk/rv fp16; lk/lv fp32 broadcast; f32x2 math.
// ============================================================================
__global__ __launch_bounds__(64) void attn11_kernel()
{
    const int bx = blockIdx.x;       // 0..31
    const int xt = bx >> 2;          // 0..7
    const int yq = bx & 3;           // y-quarter
    const int hh = blockIdx.y;
    const int b  = blockIdx.z;
    const int t  = threadIdx.x;      // 0..63
    const int yl = t >> 2;           // local y 0..15
    const int dq = t & 3;
    const int x0 = xt * TX;
    const int y0 = yq * 16;
    const int y  = y0 + yl;

    __shared__ __half rk_s[2][16][32];
    __shared__ __half rv_s[2][16][32];
    __shared__ float  lk_s[2][TX][36];
    __shared__ float  lv_s[2][TX][36];

    // rk/rv loader: 16 rows x 32 halfs = 64 thr x uint4
    const int lr  = t >> 2;          // 0..15
    const int lc8 = (t & 3) * 8;
    // lk/lv loader: 8 rows x 32 floats = 64 thr x float4
    const int xr  = t >> 3;          // 0..7
    const int lc4 = (t & 7) * 4;

    uint4 prk, prv;
    float4 plk, plv;
    u64 pmN, pmC;

    // ---- prefetch a = 0 ----
    {
        const size_t baseR = ((size_t)(b * Nn) * Nn + y0 + lr) * DFF + hh * DKk;
        prk = *(const uint4*)&g_projh[baseR + 256 + lc8];
        prv = *(const uint4*)&g_projh[baseR + 768 + lc8];
        const int baseL = ((b * Nn + x0 + xr) * Nn) * DFF + hh * DKk;
        plk = *(const float4*)&g_proj[baseL + lc4];
        plv = *(const float4*)&g_proj[baseL + 512 + lc4];
        pmN = *(const u64*)&g_maskT[((b * Nn) * Nn + y) * 64 + x0];
    }
    *(uint4*)&rk_s[0][lr][lc8] = prk;
    *(uint4*)&rv_s[0][lr][lc8] = prv;
    *(float4*)&lk_s[0][xr][lc4] = plk;
    *(float4*)&lv_s[0][xr][lc4] = plv;
    __syncthreads();

    u64 acc[TX][4];
    float l[TX];
#pragma unroll
    for (int xx = 0; xx < TX; xx++) {
        l[xx] = 0.f;
#pragma unroll
        for (int j = 0; j < 4; j++) acc[xx][j] = 0ull;
    }

    for (int a = 0; a < Nn; a++) {
        const int buf = a & 1;

        pmC = pmN;
        if (a + 1 < Nn) {   // prefetch a+1 (overlaps compute)
            const size_t baseR = ((size_t)(b * Nn + (a + 1)) * Nn + y0 + lr) * DFF + hh * DKk;
            prk = *(const uint4*)&g_projh[baseR + 256 + lc8];
            prv = *(const uint4*)&g_projh[baseR + 768 + lc8];
            const int baseL = ((b * Nn + x0 + xr) * Nn + (a + 1)) * DFF + hh * DKk;
            plk = *(const float4*)&g_proj[baseL + lc4];
            plv = *(const float4*)&g_proj[baseL + 512 + lc4];
            pmN = *(const u64*)&g_maskT[((b * Nn + (a + 1)) * Nn + y) * 64 + x0];
        }

        // ---- compute step a ----
        const uint4 hrk = *(const uint4*)&rk_s[buf][yl][dq * 8];
        const uint4 hrv = *(const uint4*)&rv_s[buf][yl][dq * 8];
        u64 rka0, rka1, rkb0, rkb1, rva0, rva1, rvb0, rvb1;
        h8_to_f32x2(hrk, rka0, rka1, rkb0, rkb1);
        h8_to_f32x2(hrv, rva0, rva1, rvb0, rvb1);

#pragma unroll
        for (int xx = 0; xx < TX; xx++) {
            const ulonglong2 lka = *(const ulonglong2*)&lk_s[buf][xx][dq * 8];
            const ulonglong2 lkb = *(const ulonglong2*)&lk_s[buf][xx][dq * 8 + 4];
            u64 s2 = mul2(lka.x, rka0);
            s2 = fma2(lka.y, rka1, s2);
            s2 = fma2(lkb.x, rkb0, s2);
            s2 = fma2(lkb.y, rkb1, s2);
            float lo, hi;
            upk2(s2, lo, hi);
            float part = lo + hi;
            part += __shfl_xor_sync(0xffffffffu, part, 1);
            part += __shfl_xor_sync(0xffffffffu, part, 2);
            const float sc = ((pmC >> (xx * 8)) & 0xffull) ? -1e9f : part;
            const float p  = __expf(sc);
            l[xx] += p;
            const u64 pp = pk2(p, p);
            const ulonglong2 lva = *(const ulonglong2*)&lv_s[buf][xx][dq * 8];
            const ulonglong2 lvb = *(const ulonglong2*)&lv_s[buf][xx][dq * 8 + 4];
            acc[xx][0] = fma2(mul2(lva.x, rva0), pp, acc[xx][0]);
            acc[xx][1] = fma2(mul2(lva.y, rva1), pp, acc[xx][1]);
            acc[xx][2] = fma2(mul2(lvb.x, rvb0), pp, acc[xx][2]);
            acc[xx][3] = fma2(mul2(lvb.y, rvb1), pp, acc[xx][3]);
        }

        // ---- store prefetched a+1 ----
        if (a + 1 < Nn) {
            const int nb = buf ^ 1;
            *(uint4*)&rk_s[nb][lr][lc8] = prk;
            *(uint4*)&rv_s[nb][lr][lc8] = prv;
            *(float4*)&lk_s[nb][xr][lc4] = plk;
            *(float4*)&lv_s[nb][xr][lc4] = plv;
            __syncthreads();
        }
    }

#pragma unroll
    for (int xx = 0; xx < TX; xx++) {
        const float inv = 1.0f / l[xx];
        const int ob = ((b * Nn + x0 + xx) * Nn + y) * Dd + hh * DKk + dq * 8;
        float a0, a1, a2, a3, a4, a5, a6, a7;
        upk2(acc[xx][0], a0, a1);
        upk2(acc[xx][1], a2, a3);
        upk2(acc[xx][2], a4, a5);
        upk2(acc[xx][3], a6, a7);
        uint4 hv;
        hv.x = h2u(__floats2half2_rn(a0 * inv, a1 * inv));
        hv.y = h2u(__floats2half2_rn(a2 * inv, a3 * inv));
        hv.z = h2u(__floats2half2_rn(a4 * inv, a5 * inv));
        hv.w = h2u(__floats2half2_rn(a6 * inv, a7 * inv));
        *(uint4*)&g_att[ob] = hv;
    }
}

// ============================================================================
// launch
// ============================================================================
extern "C" void kernel_launch(void* const* d_in, const int* in_sizes, int n_in,
                              void* d_out, int out_size)
{
    const float*         x    = (const float*)d_in[0];
    const unsigned char* mask = (const unsigned char*)d_in[1];
    const float*         Wlk  = (const float*)d_in[2];
    const float*         Wrk  = (const float*)d_in[3];
    const float*         Wlv  = (const float*)d_in[4];
    const float*         Wrv  = (const float*)d_in[5];
    const float*         Wo   = (const float*)d_in[6];
    const float*         W1   = (const float*)d_in[7];
    const float*         b1   = (const float*)d_in[8];
    const float*         W2   = (const float*)d_in[9];
    const float*         b2   = (const float*)d_in[10];
    const float*         g1   = (const float*)d_in[11];
    const float*         be1  = (const float*)d_in[12];
    const float*         g2   = (const float*)d_in[13];
    const float*         be2  = (const float*)d_in[14];
    float* out = (float*)d_out;

    k_prep<<<2880, 256>>>(Wlk, Wrk, Wlv, Wrv, Wo, W1, W2, mask);
    ln1_kernel<<<RR / 8, 256>>>(x, g1, be1);
    k_proj_tc<<<dim3(DFF / 128, RR / 128), 256>>>();
    attn11_kernel<<<dim3(32, Hh, Bb), 64>>>();
    k_wo_tc<<<dim3(Dd / 128, RR / 64), 256>>>();
    ln2_kernel<<<RR / 8, 256>>>(g2, be2);
    k_ffn1_tc<<<dim3(DFF / 128, RR / 128), 256>>>(b1);
    k_ffn2_tc<<<dim3(Dd / 128, RR / 64), 256>>>(b2, out);
}

// round 15
// speedup vs baseline: 1.0692x; 1.0692x over previous
#include <cuda_runtime.h>
#include <cuda_fp16.h>
#include <cstdint>

// ============================================================================
// EdgeTransformerLayer (B=2, N=64, D=256, H=8, DK=32, DFF=1024)
// GEMMs: mma.sync.m16n8k16 fp16, TM=128 tiles (round-13 winner config).
// proj: lk/lv -> fp32 only, rk/rv -> fp16 only (no dead stores).
// Attention: TX=8, y-split x4 (attn11, round-14 winner), fp16 rk/rv streams.
// prep + ln1 fused into one launch.
// ============================================================================

namespace {
constexpr int Bb  = 2;
constexpr int Nn  = 64;
constexpr int Dd  = 256;
constexpr int Hh  = 8;
constexpr int DKk = 32;
constexpr int DFF = 1024;
constexpr int RR  = Bb * Nn * Nn;   // 8192
constexpr int SPH = 40;             // GEMM smem row stride (halfs)
constexpr int BUFH = 128 * SPH;
constexpr int TX  = 8;
}

// ---- device-global scratch ---------------------------------------------------
__device__ float  g_h     [RR * Dd];
__device__ __half g_hh    [RR * Dd];
__device__ float  g_proj  [RR * DFF];  // fp32 valid cols: [0,256)=lk*scale, [512,768)=lv
__device__ __half g_projh [RR * DFF];  // fp16 valid cols: [256,512)=rk, [768,1024)=rv
__device__ __half g_att   [RR * Dd];
__device__ float  g_hres  [RR * Dd];
__device__ float  g_h2    [RR * Dd];
__device__ __half g_h2h   [RR * Dd];
__device__ __half g_ffn   [RR * DFF];
__device__ __half g_Wh_qkv[DFF * Dd];
__device__ __half g_Wh_o  [Dd * Dd];
__device__ __half g_Wh_1  [DFF * Dd];
__device__ __half g_Wh_2  [Dd * DFF];
__device__ unsigned char g_maskT[Bb * Nn * Nn * Nn];  // [b][a][y][x]

// ============================================================================
// helpers
// ============================================================================
__device__ __forceinline__ uint32_t smem_u32(const void* p) {
    uint32_t a;
    asm("{ .reg .u64 t; cvta.to.shared.u64 t, %1; cvt.u32.u64 %0, t; }" : "=r"(a) : "l"(p));
    return a;
}

__device__ __forceinline__ void mma_f16(float c[4],
                                        uint32_t a0, uint32_t a1, uint32_t a2, uint32_t a3,
                                        uint32_t b0, uint32_t b1) {
    asm volatile(
        "mma.sync.aligned.m16n8k16.row.col.f32.f16.f16.f32 "
        "{%0,%1,%2,%3}, {%4,%5,%6,%7}, {%8,%9}, {%0,%1,%2,%3};"
        : "+f"(c[0]), "+f"(c[1]), "+f"(c[2]), "+f"(c[3])
        : "r"(a0), "r"(a1), "r"(a2), "r"(a3), "r"(b0), "r"(b1));
}

__device__ __forceinline__ void ldsm_x4(uint32_t r[4], uint32_t addr) {
    asm volatile("ldmatrix.sync.aligned.m8n8.x4.shared.b16 {%0,%1,%2,%3}, [%4];"
                 : "=r"(r[0]), "=r"(r[1]), "=r"(r[2]), "=r"(r[3]) : "r"(addr));
}
__device__ __forceinline__ void ldsm_x2(uint32_t r[2], uint32_t addr) {
    asm volatile("ldmatrix.sync.aligned.m8n8.x2.shared.b16 {%0,%1}, [%2];"
                 : "=r"(r[0]), "=r"(r[1]) : "r"(addr));
}

__device__ __forceinline__ uint32_t h2u(__half2 h) {
    uint32_t u; asm("mov.b32 %0, %1;" : "=r"(u) : "r"(*(uint32_t*)&h)); return u;
}

typedef unsigned long long u64;
__device__ __forceinline__ u64 pk2(float lo, float hi) {
    u64 r; asm("mov.b64 %0, {%1,%2};" : "=l"(r) : "f"(lo), "f"(hi)); return r;
}
__device__ __forceinline__ void upk2(u64 v, float& lo, float& hi) {
    asm("mov.b64 {%0,%1}, %2;" : "=f"(lo), "=f"(hi) : "l"(v));
}
__device__ __forceinline__ u64 mul2(u64 a, u64 b) {
    u64 d; asm("mul.rn.f32x2 %0, %1, %2;" : "=l"(d) : "l"(a), "l"(b)); return d;
}
__device__ __forceinline__ u64 fma2(u64 a, u64 b, u64 c) {
    u64 d; asm("fma.rn.f32x2 %0, %1, %2, %3;" : "=l"(d) : "l"(a), "l"(b), "l"(c)); return d;
}

__device__ __forceinline__ void h8_to_f32x2(uint4 h, u64& a0, u64& a1, u64& b0, u64& b1) {
    const float2 f0 = __half22float2(*(__half2*)&h.x);
    const float2 f1 = __half22float2(*(__half2*)&h.y);
    const float2 f2 = __half22float2(*(__half2*)&h.z);
    const float2 f3 = __half22float2(*(__half2*)&h.w);
    a0 = pk2(f0.x, f0.y); a1 = pk2(f1.x, f1.y);
    b0 = pk2(f2.x, f2.y); b1 = pk2(f3.x, f3.y);
}

// ============================================================================
// LayerNorm body (warp per row)
// ============================================================================
__device__ __forceinline__ void ln_rows(const float* __restrict__ in,
                                        const float* __restrict__ gam,
                                        const float* __restrict__ bet,
                                        float* __restrict__ out,
                                        __half* __restrict__ outh,
                                        int rowBase)
{
    const int row  = rowBase + (threadIdx.x >> 5);
    const int lane = threadIdx.x & 31;
    const float* rp = in + (size_t)row * Dd + lane * 8;
    const float4 v0 = *(const float4*)rp;
    const float4 v1 = *(const float4*)(rp + 4);
    float s  = v0.x + v0.y + v0.z + v0.w + v1.x + v1.y + v1.z + v1.w;
    float s2 = v0.x*v0.x + v0.y*v0.y + v0.z*v0.z + v0.w*v0.w
             + v1.x*v1.x + v1.y*v1.y + v1.z*v1.z + v1.w*v1.w;
#pragma unroll
    for (int o = 16; o; o >>= 1) {
        s  += __shfl_xor_sync(0xffffffffu, s,  o);
        s2 += __shfl_xor_sync(0xffffffffu, s2, o);
    }
    const float mean = s * (1.0f / Dd);
    const float var  = s2 * (1.0f / Dd) - mean * mean;
    const float inv  = rsqrtf(var + 1e-5f);
    const float4 g0 = *(const float4*)(gam + lane * 8);
    const float4 g1 = *(const float4*)(gam + lane * 8 + 4);
    const float4 b0 = *(const float4*)(bet + lane * 8);
    const float4 b1 = *(const float4*)(bet + lane * 8 + 4);
    float4 o0, o1;
    o0.x = (v0.x - mean) * inv * g0.x + b0.x;
    o0.y = (v0.y - mean) * inv * g0.y + b0.y;
    o0.z = (v0.z - mean) * inv * g0.z + b0.z;
    o0.w = (v0.w - mean) * inv * g0.w + b0.w;
    o1.x = (v1.x - mean) * inv * g1.x + b1.x;
    o1.y = (v1.y - mean) * inv * g1.y + b1.y;
    o1.z = (v1.z - mean) * inv * g1.z + b1.z;
    o1.w = (v1.w - mean) * inv * g1.w + b1.w;
    float* op = out + (size_t)row * Dd + lane * 8;
    *(float4*)op       = o0;
    *(float4*)(op + 4) = o1;
    uint4 hv;
    hv.x = h2u(__floats2half2_rn(o0.x, o0.y));
    hv.y = h2u(__floats2half2_rn(o0.z, o0.w));
    hv.z = h2u(__floats2half2_rn(o1.x, o1.y));
    hv.w = h2u(__floats2half2_rn(o1.z, o1.w));
    *(uint4*)(outh + (size_t)row * Dd + lane * 8) = hv;
}

// ============================================================================
// fused prep + ln1:
//   id <  832 : weight transpose tiles
//   id < 2880 : mask transpose
//   else      : ln1 rows (8 per block)
// ============================================================================
__device__ __forceinline__ __half* trh_dst(int which) {
    switch (which) {
        case 0: return g_Wh_qkv;
        case 1: return g_Wh_qkv + 256 * 256;
        case 2: return g_Wh_qkv + 512 * 256;
        case 3: return g_Wh_qkv + 768 * 256;
        case 4: return g_Wh_o;
        case 5: return g_Wh_1;
        default: return g_Wh_2;
    }
}

__global__ __launch_bounds__(256) void k_prep_ln1(const float* __restrict__ Wlk,
                                                  const float* __restrict__ Wrk,
                                                  const float* __restrict__ Wlv,
                                                  const float* __restrict__ Wrv,
                                                  const float* __restrict__ Wo,
                                                  const float* __restrict__ W1,
                                                  const float* __restrict__ W2,
                                                  const unsigned char* __restrict__ mask,
                                                  const float* __restrict__ x,
                                                  const float* __restrict__ g1,
                                                  const float* __restrict__ be1)
{
    const int id = blockIdx.x;
    if (id >= 2880) {                 // ln1
        ln_rows(x, g1, be1, g_h, g_hh, (id - 2880) * 8);
        return;
    }
    if (id >= 832) {                  // mask transpose
        const int g = (id - 832) * 256 + threadIdx.x;
        const int xx = g & 63;
        const int yy = (g >> 6) & 63;
        const int a  = (g >> 12) & 63;
        const int bb = g >> 18;
        g_maskT[g] = mask[(((bb * 64 + xx) * 64 + a) * 64) + yy];
        return;
    }

    __shared__ float tile[32][33];
    const float* src;
    __half* dst;
    float scale = 1.0f;
    int K, N, n0, k0;
    if (id < 320) {
        const int w = id >> 6;
        const int tl = id & 63;
        src = (w == 0) ? Wlk : (w == 1) ? Wrk : (w == 2) ? Wlv : (w == 3) ? Wrv : Wo;
        dst = trh_dst(w);
        if (w == 0) scale = 0.17677669529663687f;   // 1/sqrt(32)
        K = 256; N = 256;
        n0 = (tl & 7) * 32; k0 = (tl >> 3) * 32;
    } else if (id < 576) {
        const int tl = id - 320;
        src = W1; dst = g_Wh_1; K = 256; N = 1024;
        n0 = (tl & 31) * 32; k0 = (tl >> 5) * 32;
    } else {
        const int tl = id - 576;
        src = W2; dst = g_Wh_2; K = 1024; N = 256;
        n0 = (tl & 7) * 32; k0 = (tl >> 3) * 32;
    }
    const int tx = threadIdx.x & 31;
    const int ty = threadIdx.x >> 5;
#pragma unroll
    for (int r = ty; r < 32; r += 8)
        tile[r][tx] = src[(size_t)(k0 + r) * N + n0 + tx];
    __syncthreads();
#pragma unroll
    for (int r = ty; r < 32; r += 8)
        dst[(size_t)(n0 + r) * K + k0 + tx] = __float2half_rn(tile[tx][r] * scale);
}

__global__ __launch_bounds__(256) void ln2_kernel(const float* __restrict__ g2,
                                                  const float* __restrict__ be2)
{ ln_rows(g_hres, g2, be2, g_h2, g_h2h, blockIdx.x * 8); }

// ============================================================================
// fp16 mma GEMM, 128x128 CTA tile, 8 warps (2x4), warp tile 64x32, K chunks 32.
// EPI: 0 proj (fp32 for lk/lv tiles, fp16 for rk/rv tiles); 1 +Cadd f32;
//      3 +bias+Cadd f32; 4 +bias,relu -> fp16.
// ============================================================================
template <int K, int NC, int EPI>
__device__ __forceinline__ void gemm_hh(const __half* __restrict__ A,
                                        const __half* __restrict__ Wh,
                                        const float* __restrict__ Cadd,
                                        const float* __restrict__ bias,
                                        void* __restrict__ Cout)
{
    constexpr int NCH = K / 32;
    __shared__ __half As[2][BUFH];
    __shared__ __half Bs[2][BUFH];
    constexpr uint32_t BUFBYTES = BUFH * 2;

    const int t    = threadIdx.x;
    const int lane = t & 31;
    const int wid  = t >> 5;
    const int gr   = lane >> 2;
    const int tig  = lane & 3;
    const int wm   = (wid & 1) * 64;
    const int wn   = (wid >> 1) * 32;

    const int bm = blockIdx.y * 128;
    const int bn = blockIdx.x * 128;

    const uint32_t a_base = smem_u32(As) +
        ((wm + (lane & 15)) * SPH + ((lane >> 4) & 1) * 8) * 2;
    const uint32_t b_base = smem_u32(Bs) +
        ((wn + (lane & 7)) * SPH + ((lane >> 3) & 1) * 8) * 2;

    const int lrow = t >> 1;
    const int lko  = (t & 1) * 16;
    const uint4* Agh = (const uint4*)(A  + (size_t)(bm + lrow) * K);
    const uint4* Bgh = (const uint4*)(Wh + (size_t)(bn + lrow) * K);
    const int    gi  = (t & 1) * 2;

    uint4 pa0, pa1, pb0, pb1;
    pa0 = Agh[gi];     pa1 = Agh[gi + 1];
    pb0 = Bgh[gi];     pb1 = Bgh[gi + 1];

    float acc[4][4][4];
#pragma unroll
    for (int im = 0; im < 4; im++)
#pragma unroll
        for (int in = 0; in < 4; in++)
#pragma unroll
            for (int j = 0; j < 4; j++) acc[im][in][j] = 0.f;

    {
        __half* asw = &As[0][lrow * SPH + lko];
        *(uint4*)asw       = pa0;
        *(uint4*)(asw + 8) = pa1;
        __half* bsw = &Bs[0][lrow * SPH + lko];
        *(uint4*)bsw       = pb0;
        *(uint4*)(bsw + 8) = pb1;
    }
    __syncthreads();

    for (int c = 0; c < NCH; c++) {
        const int buf = c & 1;

        if (c + 1 < NCH) {
            pa0 = Agh[gi + (c + 1) * 4];
            pa1 = Agh[gi + (c + 1) * 4 + 1];
            pb0 = Bgh[gi + (c + 1) * 4];
            pb1 = Bgh[gi + (c + 1) * 4 + 1];
        }

        const uint32_t a_addr = a_base + buf * BUFBYTES;
        const uint32_t b_addr = b_base + buf * BUFBYTES;
#pragma unroll
        for (int ks = 0; ks < 2; ks++) {
            uint32_t af[4][4], bf[4][2];
#pragma unroll
            for (int im = 0; im < 4; im++)
                ldsm_x4(af[im], a_addr + (uint32_t)(im * 16 * SPH * 2 + ks * 32));
#pragma unroll
            for (int in = 0; in < 4; in++)
                ldsm_x2(bf[in], b_addr + (uint32_t)(in * 8 * SPH * 2 + ks * 32));
#pragma unroll
            for (int im = 0; im < 4; im++)
#pragma unroll
                for (int in = 0; in < 4; in++)
                    mma_f16(acc[im][in], af[im][0], af[im][1], af[im][2], af[im][3],
                            bf[in][0], bf[in][1]);
        }

        if (c + 1 < NCH) {
            const int nb = buf ^ 1;
            __half* asw = &As[nb][lrow * SPH + lko];
            *(uint4*)asw       = pa0;
            *(uint4*)(asw + 8) = pa1;
            __half* bsw = &Bs[nb][lrow * SPH + lko];
            *(uint4*)bsw       = pb0;
            *(uint4*)(bsw + 8) = pb1;
            __syncthreads();
        }
    }

    // epilogue: proj writes rk/rv tiles as fp16 ONLY, lk/lv tiles as fp32 ONLY
    const bool rkrv = (EPI == 0) && ((bn >= 256 && bn < 512) || bn >= 768);
#pragma unroll
    for (int im = 0; im < 4; im++) {
        const int r0 = bm + wm + im * 16 + gr;
#pragma unroll
        for (int in = 0; in < 4; in++) {
            const int col = bn + wn + in * 8 + 2 * tig;
            float2 v0 = make_float2(acc[im][in][0], acc[im][in][1]);
            float2 v1 = make_float2(acc[im][in][2], acc[im][in][3]);
            if (EPI == 3 || EPI == 4) {
                const float2 bb = *(const float2*)&bias[col];
                v0.x += bb.x; v0.y += bb.y;
                v1.x += bb.x; v1.y += bb.y;
            }
            if (EPI == 4) {
                v0.x = fmaxf(v0.x, 0.f); v0.y = fmaxf(v0.y, 0.f);
                v1.x = fmaxf(v1.x, 0.f); v1.y = fmaxf(v1.y, 0.f);
            }
            if (EPI == 1 || EPI == 3) {
                const float2 c0 = *(const float2*)&Cadd[(size_t)r0 * NC + col];
                const float2 c1 = *(const float2*)&Cadd[(size_t)(r0 + 8) * NC + col];
                v0.x += c0.x; v0.y += c0.y;
                v1.x += c1.x; v1.y += c1.y;
            }
            if (EPI == 4) {
                __half* Ch = (__half*)Cout;
                *(uint32_t*)&Ch[(size_t)r0 * NC + col] =
                    h2u(__floats2half2_rn(v0.x, v0.y));
                *(uint32_t*)&Ch[(size_t)(r0 + 8) * NC + col] =
                    h2u(__floats2half2_rn(v1.x, v1.y));
            } else if (EPI == 0 && rkrv) {
                *(uint32_t*)&g_projh[(size_t)r0 * NC + col] =
                    h2u(__floats2half2_rn(v0.x, v0.y));
                *(uint32_t*)&g_projh[(size_t)(r0 + 8) * NC + col] =
                    h2u(__floats2half2_rn(v1.x, v1.y));
            } else {
                float* Cf = (float*)Cout;
                *(float2*)&Cf[(size_t)r0 * NC + col]       = v0;
                *(float2*)&Cf[(size_t)(r0 + 8) * NC + col] = v1;
            }
        }
    }
}

__global__ __launch_bounds__(256, 2) void k_proj_tc()
{ gemm_hh<Dd, DFF, 0>(g_hh, g_Wh_qkv, nullptr, nullptr, g_proj); }

__global__ __launch_bounds__(256, 2) void k_wo_tc()
{ gemm_hh<Dd, Dd, 1>(g_att, g_Wh_o, g_h, nullptr, g_hres); }

__global__ __launch_bounds__(256, 2) void k_ffn1_tc(const float* __restrict__ b1)
{ gemm_hh<Dd, DFF, 4>(g_h2h, g_Wh_1, nullptr, b1, g_ffn); }

__global__ __launch_bounds__(256, 2) void k_ffn2_tc(const float* __restrict__ b2,
                                                    float* __restrict__ out)
{ gemm_hh<DFF, Dd, 3>(g_ffn, g_Wh_2, g_h2, b2, out); }

// ============================================================================
// Triangle attention (attn11): TX=8, 16 y-rows/CTA, 64 threads, 512 CTAs.
// rk/rv fp16 streams; lk/lv fp32 broadcast; f32x2 math; no-max softmax.
// ============================================================================
__global__ __launch_bounds__(64) void attn11_kernel()
{
    const int bx = blockIdx.x;       // 0..31
    const int xt = bx >> 2;
    const int yq = bx & 3;
    const int hh = blockIdx.y;
    const int b  = blockIdx.z;
    const int t  = threadIdx.x;      // 0..63
    const int yl = t >> 2;           // 0..15
    const int dq = t & 3;
    const int x0 = xt * TX;
    const int y0 = yq * 16;
    const int y  = y0 + yl;

    __shared__ __half rk_s[2][16][32];
    __shared__ __half rv_s[2][16][32];
    __shared__ float  lk_s[2][TX][36];
    __shared__ float  lv_s[2][TX][36];

    const int lr  = t >> 2;
    const int lc8 = (t & 3) * 8;
    const int xr  = t >> 3;
    const int lc4 = (t & 7) * 4;

    uint4 prk, prv;
    float4 plk, plv;
    u64 pmN, pmC;

    {
        const size_t baseR = ((size_t)(b * Nn) * Nn + y0 + lr) * DFF + hh * DKk;
        prk = *(const uint4*)&g_projh[baseR + 256 + lc8];
        prv = *(const uint4*)&g_projh[baseR + 768 + lc8];
        const int baseL = ((b * Nn + x0 + xr) * Nn) * DFF + hh * DKk;
        plk = *(const float4*)&g_proj[baseL + lc4];
        plv = *(const float4*)&g_proj[baseL + 512 + lc4];
        pmN = *(const u64*)&g_maskT[((b * Nn) * Nn + y) * 64 + x0];
    }
    *(uint4*)&rk_s[0][lr][lc8] = prk;
    *(uint4*)&rv_s[0][lr][lc8] = prv;
    *(float4*)&lk_s[0][xr][lc4] = plk;
    *(float4*)&lv_s[0][xr][lc4] = plv;
    __syncthreads();

    u64 acc[TX][4];
    float l[TX];
#pragma unroll
    for (int xx = 0; xx < TX; xx++) {
        l[xx] = 0.f;
#pragma unroll
        for (int j = 0; j < 4; j++) acc[xx][j] = 0ull;
    }

    for (int a = 0; a < Nn; a++) {
        const int buf = a & 1;

        pmC = pmN;
        if (a + 1 < Nn) {
            const size_t baseR = ((size_t)(b * Nn + (a + 1)) * Nn + y0 + lr) * DFF + hh * DKk;
            prk = *(const uint4*)&g_projh[baseR + 256 + lc8];
            prv = *(const uint4*)&g_projh[baseR + 768 + lc8];
            const int baseL = ((b * Nn + x0 + xr) * Nn + (a + 1)) * DFF + hh * DKk;
            plk = *(const float4*)&g_proj[baseL + lc4];
            plv = *(const float4*)&g_proj[baseL + 512 + lc4];
            pmN = *(const u64*)&g_maskT[((b * Nn + (a + 1)) * Nn + y) * 64 + x0];
        }

        const uint4 hrk = *(const uint4*)&rk_s[buf][yl][dq * 8];
        const uint4 hrv = *(const uint4*)&rv_s[buf][yl][dq * 8];
        u64 rka0, rka1, rkb0, rkb1, rva0, rva1, rvb0, rvb1;
        h8_to_f32x2(hrk, rka0, rka1, rkb0, rkb1);
        h8_to_f32x2(hrv, rva0, rva1, rvb0, rvb1);

#pragma unroll
        for (int xx = 0; xx < TX; xx++) {
            const ulonglong2 lka = *(const ulonglong2*)&lk_s[buf][xx][dq * 8];
            const ulonglong2 lkb = *(const ulonglong2*)&lk_s[buf][xx][dq * 8 + 4];
            u64 s2 = mul2(lka.x, rka0);
            s2 = fma2(lka.y, rka1, s2);
            s2 = fma2(lkb.x, rkb0, s2);
            s2 = fma2(lkb.y, rkb1, s2);
            float lo, hi;
            upk2(s2, lo, hi);
            float part = lo + hi;
            part += __shfl_xor_sync(0xffffffffu, part, 1);
            part += __shfl_xor_sync(0xffffffffu, part, 2);
            const float sc = ((pmC >> (xx * 8)) & 0xffull) ? -1e9f : part;
            const float p  = __expf(sc);
            l[xx] += p;
            const u64 pp = pk2(p, p);
            const ulonglong2 lva = *(const ulonglong2*)&lv_s[buf][xx][dq * 8];
            const ulonglong2 lvb = *(const ulonglong2*)&lv_s[buf][xx][dq * 8 + 4];
            acc[xx][0] = fma2(mul2(lva.x, rva0), pp, acc[xx][0]);
            acc[xx][1] = fma2(mul2(lva.y, rva1), pp, acc[xx][1]);
            acc[xx][2] = fma2(mul2(lvb.x, rvb0), pp, acc[xx][2]);
            acc[xx][3] = fma2(mul2(lvb.y, rvb1), pp, acc[xx][3]);
        }

        if (a + 1 < Nn) {
            const int nb = buf ^ 1;
            *(uint4*)&rk_s[nb][lr][lc8] = prk;
            *(uint4*)&rv_s[nb][lr][lc8] = prv;
            *(float4*)&lk_s[nb][xr][lc4] = plk;
            *(float4*)&lv_s[nb][xr][lc4] = plv;
            __syncthreads();
        }
    }

#pragma unroll
    for (int xx = 0; xx < TX; xx++) {
        const float inv = 1.0f / l[xx];
        const int ob = ((b * Nn + x0 + xx) * Nn + y) * Dd + hh * DKk + dq * 8;
        float a0, a1, a2, a3, a4, a5, a6, a7;
        upk2(acc[xx][0], a0, a1);
        upk2(acc[xx][1], a2, a3);
        upk2(acc[xx][2], a4, a5);
        upk2(acc[xx][3], a6, a7);
        uint4 hv;
        hv.x = h2u(__floats2half2_rn(a0 * inv, a1 * inv));
        hv.y = h2u(__floats2half2_rn(a2 * inv, a3 * inv));
        hv.z = h2u(__floats2half2_rn(a4 * inv, a5 * inv));
        hv.w = h2u(__floats2half2_rn(a6 * inv, a7 * inv));
        *(uint4*)&g_att[ob] = hv;
    }
}

// ============================================================================
// launch
// ============================================================================
extern "C" void kernel_launch(void* const* d_in, const int* in_sizes, int n_in,
                              void* d_out, int out_size)
{
    const float*         x    = (const float*)d_in[0];
    const unsigned char* mask = (const unsigned char*)d_in[1];
    const float*         Wlk  = (const float*)d_in[2];
    const float*         Wrk  = (const float*)d_in[3];
    const float*         Wlv  = (const float*)d_in[4];
    const float*         Wrv  = (const float*)d_in[5];
    const float*         Wo   = (const float*)d_in[6];
    const float*         W1   = (const float*)d_in[7];
    const float*         b1   = (const float*)d_in[8];
    const float*         W2   = (const float*)d_in[9];
    const float*         b2   = (const float*)d_in[10];
    const float*         g1   = (const float*)d_in[11];
    const float*         be1  = (const float*)d_in[12];
    const float*         g2   = (const float*)d_in[13];
    const float*         be2  = (const float*)d_in[14];
    float* out = (float*)d_out;

    k_prep_ln1<<<2880 + RR / 8, 256>>>(Wlk, Wrk, Wlv, Wrv, Wo, W1, W2, mask,
                                       x, g1, be1);
    k_proj_tc<<<dim3(DFF / 128, RR / 128), 256>>>();
    attn11_kernel<<<dim3(32, Hh, Bb), 64>>>();
    k_wo_tc<<<dim3(Dd / 128, RR / 128), 256>>>();
    ln2_kernel<<<RR / 8, 256>>>(g2, be2);
    k_ffn1_tc<<<dim3(DFF / 128, RR / 128), 256>>>(b1);
    k_ffn2_tc<<<dim3(Dd / 128, RR / 128), 256>>>(b2, out);
}

// round 16
// speedup vs baseline: 1.1479x; 1.0737x over previous
#include <cuda_runtime.h>
#include <cuda_fp16.h>
#include <cstdint>

// ============================================================================
// EdgeTransformerLayer (B=2, N=64, D=256, H=8, DK=32, DFF=1024)
// GEMMs: mma.sync.m16n8k16 fp16, 128x128 tiles, cp.async 3-stage pipeline.
// proj: lk/lv -> fp32, rk/rv -> fp16 (single-precision stores, no dead data).
// Attention: attn11 (TX=8, 16 y-rows/CTA, 64 thr, 512 CTAs), fp16 rk/rv.
// prep + ln1 fused.
// ============================================================================

namespace {
constexpr int Bb  = 2;
constexpr int Nn  = 64;
constexpr int Dd  = 256;
constexpr int Hh  = 8;
constexpr int DKk = 32;
constexpr int DFF = 1024;
constexpr int RR  = Bb * Nn * Nn;   // 8192
constexpr int SPH = 40;             // GEMM smem row stride (halfs) = 80B
constexpr int BUFH = 128 * SPH;     // halfs per stage per operand
constexpr int DSMEM = 3 * 2 * BUFH * 2;  // 61440 bytes (3 stages x (A+B))
constexpr int TX  = 8;
}

// ---- device-global scratch ---------------------------------------------------
__device__ float  g_h     [RR * Dd];
__device__ __half g_hh    [RR * Dd];
__device__ float  g_proj  [RR * DFF];  // fp32 valid cols: [0,256)=lk*scale, [512,768)=lv
__device__ __half g_projh [RR * DFF];  // fp16 valid cols: [256,512)=rk, [768,1024)=rv
__device__ __half g_att   [RR * Dd];
__device__ float  g_hres  [RR * Dd];
__device__ float  g_h2    [RR * Dd];
__device__ __half g_h2h   [RR * Dd];
__device__ __half g_ffn   [RR * DFF];
__device__ __half g_Wh_qkv[DFF * Dd];
__device__ __half g_Wh_o  [Dd * Dd];
__device__ __half g_Wh_1  [DFF * Dd];
__device__ __half g_Wh_2  [Dd * DFF];
__device__ unsigned char g_maskT[Bb * Nn * Nn * Nn];  // [b][a][y][x]

// ============================================================================
// helpers
// ============================================================================
__device__ __forceinline__ uint32_t smem_u32(const void* p) {
    uint32_t a;
    asm("{ .reg .u64 t; cvta.to.shared.u64 t, %1; cvt.u32.u64 %0, t; }" : "=r"(a) : "l"(p));
    return a;
}

__device__ __forceinline__ void mma_f16(float c[4],
                                        uint32_t a0, uint32_t a1, uint32_t a2, uint32_t a3,
                                        uint32_t b0, uint32_t b1) {
    asm volatile(
        "mma.sync.aligned.m16n8k16.row.col.f32.f16.f16.f32 "
        "{%0,%1,%2,%3}, {%4,%5,%6,%7}, {%8,%9}, {%0,%1,%2,%3};"
        : "+f"(c[0]), "+f"(c[1]), "+f"(c[2]), "+f"(c[3])
        : "r"(a0), "r"(a1), "r"(a2), "r"(a3), "r"(b0), "r"(b1));
}

__device__ __forceinline__ void ldsm_x4(uint32_t r[4], uint32_t addr) {
    asm volatile("ldmatrix.sync.aligned.m8n8.x4.shared.b16 {%0,%1,%2,%3}, [%4];"
                 : "=r"(r[0]), "=r"(r[1]), "=r"(r[2]), "=r"(r[3]) : "r"(addr));
}
__device__ __forceinline__ void ldsm_x2(uint32_t r[2], uint32_t addr) {
    asm volatile("ldmatrix.sync.aligned.m8n8.x2.shared.b16 {%0,%1}, [%2];"
                 : "=r"(r[0]), "=r"(r[1]) : "r"(addr));
}

__device__ __forceinline__ uint32_t h2u(__half2 h) {
    uint32_t u; asm("mov.b32 %0, %1;" : "=r"(u) : "r"(*(uint32_t*)&h)); return u;
}

// cp.async
__device__ __forceinline__ void cp16(uint32_t dst, const void* src) {
    asm volatile("cp.async.cg.shared.global [%0], [%1], 16;"
                 :: "r"(dst), "l"(src) : "memory");
}
#define CP_COMMIT() asm volatile("cp.async.commit_group;" ::: "memory")
#define CP_WAIT1()  asm volatile("cp.async.wait_group 1;" ::: "memory")
#define CP_WAIT0()  asm volatile("cp.async.wait_group 0;" ::: "memory")

typedef unsigned long long u64;
__device__ __forceinline__ u64 pk2(float lo, float hi) {
    u64 r; asm("mov.b64 %0, {%1,%2};" : "=l"(r) : "f"(lo), "f"(hi)); return r;
}
__device__ __forceinline__ void upk2(u64 v, float& lo, float& hi) {
    asm("mov.b64 {%0,%1}, %2;" : "=f"(lo), "=f"(hi) : "l"(v));
}
__device__ __forceinline__ u64 mul2(u64 a, u64 b) {
    u64 d; asm("mul.rn.f32x2 %0, %1, %2;" : "=l"(d) : "l"(a), "l"(b)); return d;
}
__device__ __forceinline__ u64 fma2(u64 a, u64 b, u64 c) {
    u64 d; asm("fma.rn.f32x2 %0, %1, %2, %3;" : "=l"(d) : "l"(a), "l"(b), "l"(c)); return d;
}

__device__ __forceinline__ void h8_to_f32x2(uint4 h, u64& a0, u64& a1, u64& b0, u64& b1) {
    const float2 f0 = __half22float2(*(__half2*)&h.x);
    const float2 f1 = __half22float2(*(__half2*)&h.y);
    const float2 f2 = __half22float2(*(__half2*)&h.z);
    const float2 f3 = __half22float2(*(__half2*)&h.w);
    a0 = pk2(f0.x, f0.y); a1 = pk2(f1.x, f1.y);
    b0 = pk2(f2.x, f2.y); b1 = pk2(f3.x, f3.y);
}

// ============================================================================
// LayerNorm body (warp per row)
// ============================================================================
__device__ __forceinline__ void ln_rows(const float* __restrict__ in,
                                        const float* __restrict__ gam,
                                        const float* __restrict__ bet,
                                        float* __restrict__ out,
                                        __half* __restrict__ outh,
                                        int rowBase)
{
    const int row  = rowBase + (threadIdx.x >> 5);
    const int lane = threadIdx.x & 31;
    const float* rp = in + (size_t)row * Dd + lane * 8;
    const float4 v0 = *(const float4*)rp;
    const float4 v1 = *(const float4*)(rp + 4);
    float s  = v0.x + v0.y + v0.z + v0.w + v1.x + v1.y + v1.z + v1.w;
    float s2 = v0.x*v0.x + v0.y*v0.y + v0.z*v0.z + v0.w*v0.w
             + v1.x*v1.x + v1.y*v1.y + v1.z*v1.z + v1.w*v1.w;
#pragma unroll
    for (int o = 16; o; o >>= 1) {
        s  += __shfl_xor_sync(0xffffffffu, s,  o);
        s2 += __shfl_xor_sync(0xffffffffu, s2, o);
    }
    const float mean = s * (1.0f / Dd);
    const float var  = s2 * (1.0f / Dd) - mean * mean;
    const float inv  = rsqrtf(var + 1e-5f);
    const float4 g0 = *(const float4*)(gam + lane * 8);
    const float4 g1 = *(const float4*)(gam + lane * 8 + 4);
    const float4 b0 = *(const float4*)(bet + lane * 8);
    const float4 b1 = *(const float4*)(bet + lane * 8 + 4);
    float4 o0, o1;
    o0.x = (v0.x - mean) * inv * g0.x + b0.x;
    o0.y = (v0.y - mean) * inv * g0.y + b0.y;
    o0.z = (v0.z - mean) * inv * g0.z + b0.z;
    o0.w = (v0.w - mean) * inv * g0.w + b0.w;
    o1.x = (v1.x - mean) * inv * g1.x + b1.x;
    o1.y = (v1.y - mean) * inv * g1.y + b1.y;
    o1.z = (v1.z - mean) * inv * g1.z + b1.z;
    o1.w = (v1.w - mean) * inv * g1.w + b1.w;
    float* op = out + (size_t)row * Dd + lane * 8;
    *(float4*)op       = o0;
    *(float4*)(op + 4) = o1;
    uint4 hv;
    hv.x = h2u(__floats2half2_rn(o0.x, o0.y));
    hv.y = h2u(__floats2half2_rn(o0.z, o0.w));
    hv.z = h2u(__floats2half2_rn(o1.x, o1.y));
    hv.w = h2u(__floats2half2_rn(o1.z, o1.w));
    *(uint4*)(outh + (size_t)row * Dd + lane * 8) = hv;
}

// ============================================================================
// fused prep + ln1
// ============================================================================
__device__ __forceinline__ __half* trh_dst(int which) {
    switch (which) {
        case 0: return g_Wh_qkv;
        case 1: return g_Wh_qkv + 256 * 256;
        case 2: return g_Wh_qkv + 512 * 256;
        case 3: return g_Wh_qkv + 768 * 256;
        case 4: return g_Wh_o;
        case 5: return g_Wh_1;
        default: return g_Wh_2;
    }
}

__global__ __launch_bounds__(256) void k_prep_ln1(const float* __restrict__ Wlk,
                                                  const float* __restrict__ Wrk,
                                                  const float* __restrict__ Wlv,
                                                  const float* __restrict__ Wrv,
                                                  const float* __restrict__ Wo,
                                                  const float* __restrict__ W1,
                                                  const float* __restrict__ W2,
                                                  const unsigned char* __restrict__ mask,
                                                  const float* __restrict__ x,
                                                  const float* __restrict__ g1,
                                                  const float* __restrict__ be1)
{
    const int id = blockIdx.x;
    if (id >= 2880) {
        ln_rows(x, g1, be1, g_h, g_hh, (id - 2880) * 8);
        return;
    }
    if (id >= 832) {
        const int g = (id - 832) * 256 + threadIdx.x;
        const int xx = g & 63;
        const int yy = (g >> 6) & 63;
        const int a  = (g >> 12) & 63;
        const int bb = g >> 18;
        g_maskT[g] = mask[(((bb * 64 + xx) * 64 + a) * 64) + yy];
        return;
    }

    __shared__ float tile[32][33];
    const float* src;
    __half* dst;
    float scale = 1.0f;
    int K, N, n0, k0;
    if (id < 320) {
        const int w = id >> 6;
        const int tl = id & 63;
        src = (w == 0) ? Wlk : (w == 1) ? Wrk : (w == 2) ? Wlv : (w == 3) ? Wrv : Wo;
        dst = trh_dst(w);
        if (w == 0) scale = 0.17677669529663687f;   // 1/sqrt(32)
        K = 256; N = 256;
        n0 = (tl & 7) * 32; k0 = (tl >> 3) * 32;
    } else if (id < 576) {
        const int tl = id - 320;
        src = W1; dst = g_Wh_1; K = 256; N = 1024;
        n0 = (tl & 31) * 32; k0 = (tl >> 5) * 32;
    } else {
        const int tl = id - 576;
        src = W2; dst = g_Wh_2; K = 1024; N = 256;
        n0 = (tl & 7) * 32; k0 = (tl >> 3) * 32;
    }
    const int tx = threadIdx.x & 31;
    const int ty = threadIdx.x >> 5;
#pragma unroll
    for (int r = ty; r < 32; r += 8)
        tile[r][tx] = src[(size_t)(k0 + r) * N + n0 + tx];
    __syncthreads();
#pragma unroll
    for (int r = ty; r < 32; r += 8)
        dst[(size_t)(n0 + r) * K + k0 + tx] = __float2half_rn(tile[tx][r] * scale);
}

__global__ __launch_bounds__(256) void ln2_kernel(const float* __restrict__ g2,
                                                  const float* __restrict__ be2)
{ ln_rows(g_hres, g2, be2, g_h2, g_h2h, blockIdx.x * 8); }

// ============================================================================
// fp16 mma GEMM, 128x128 CTA tile, cp.async 3-stage pipeline.
// EPI: 0 proj (fp32 lk/lv tiles, fp16 rk/rv tiles); 1 +Cadd f32;
//      3 +bias+Cadd f32; 4 +bias,relu -> fp16.
// ============================================================================
template <int K, int NC, int EPI>
__device__ __forceinline__ void gemm_hh(const __half* __restrict__ A,
                                        const __half* __restrict__ Wh,
                                        const float* __restrict__ Cadd,
                                        const float* __restrict__ bias,
                                        void* __restrict__ Cout)
{
    constexpr int NCH = K / 32;
    extern __shared__ __half dsm[];
    __half* As = dsm;                 // [3][BUFH]
    __half* Bs = dsm + 3 * BUFH;      // [3][BUFH]
    constexpr uint32_t STB = BUFH * 2;  // stage stride in bytes

    const int t    = threadIdx.x;
    const int lane = t & 31;
    const int wid  = t >> 5;
    const int gr   = lane >> 2;
    const int tig  = lane & 3;
    const int wm   = (wid & 1) * 64;
    const int wn   = (wid >> 1) * 32;

    const int bm = blockIdx.y * 128;
    const int bn = blockIdx.x * 128;

    const uint32_t as0 = smem_u32(As);
    const uint32_t bs0 = smem_u32(Bs);
    const uint32_t a_base = as0 + ((wm + (lane & 15)) * SPH + ((lane >> 4) & 1) * 8) * 2;
    const uint32_t b_base = bs0 + ((wn + (lane & 7)) * SPH + ((lane >> 3) & 1) * 8) * 2;

    // loader: row = t>>1, 16 halfs at offset (t&1)*16
    const int lrow = t >> 1;
    const int lko  = (t & 1) * 16;
    const __half* Ag = A  + (size_t)(bm + lrow) * K + lko;
    const __half* Bg = Wh + (size_t)(bn + lrow) * K + lko;
    const uint32_t aws = as0 + (uint32_t)((lrow * SPH + lko) * 2);
    const uint32_t bws = bs0 + (uint32_t)((lrow * SPH + lko) * 2);

    float acc[4][4][4];
#pragma unroll
    for (int im = 0; im < 4; im++)
#pragma unroll
        for (int in = 0; in < 4; in++)
#pragma unroll
            for (int j = 0; j < 4; j++) acc[im][in][j] = 0.f;

    // prologue: stages 0 and 1 in flight
#pragma unroll
    for (int c = 0; c < 2; c++) {
        const uint32_t so = (uint32_t)(c % 3) * STB;
        cp16(aws + so,      Ag + c * 32);
        cp16(aws + so + 16, Ag + c * 32 + 8);
        cp16(bws + so,      Bg + c * 32);
        cp16(bws + so + 16, Bg + c * 32 + 8);
        CP_COMMIT();
    }

    for (int c = 0; c < NCH; c++) {
        if (c == NCH - 1) CP_WAIT0(); else CP_WAIT1();
        __syncthreads();

        if (c + 2 < NCH) {              // issue stage c+2 (buffer freed by compute(c-1))
            const uint32_t so = (uint32_t)((c + 2) % 3) * STB;
            cp16(aws + so,      Ag + (c + 2) * 32);
            cp16(aws + so + 16, Ag + (c + 2) * 32 + 8);
            cp16(bws + so,      Bg + (c + 2) * 32);
            cp16(bws + so + 16, Bg + (c + 2) * 32 + 8);
            CP_COMMIT();
        }

        const uint32_t so = (uint32_t)(c % 3) * STB;
        const uint32_t a_addr = a_base + so;
        const uint32_t b_addr = b_base + so;
#pragma unroll
        for (int ks = 0; ks < 2; ks++) {
            uint32_t af[4][4], bf[4][2];
#pragma unroll
            for (int im = 0; im < 4; im++)
                ldsm_x4(af[im], a_addr + (uint32_t)(im * 16 * SPH * 2 + ks * 32));
#pragma unroll
            for (int in = 0; in < 4; in++)
                ldsm_x2(bf[in], b_addr + (uint32_t)(in * 8 * SPH * 2 + ks * 32));
#pragma unroll
            for (int im = 0; im < 4; im++)
#pragma unroll
                for (int in = 0; in < 4; in++)
                    mma_f16(acc[im][in], af[im][0], af[im][1], af[im][2], af[im][3],
                            bf[in][0], bf[in][1]);
        }
    }

    // epilogue: proj writes rk/rv tiles fp16 ONLY, lk/lv tiles fp32 ONLY
    const bool rkrv = (EPI == 0) && ((bn >= 256 && bn < 512) || bn >= 768);
#pragma unroll
    for (int im = 0; im < 4; im++) {
        const int r0 = bm + wm + im * 16 + gr;
#pragma unroll
        for (int in = 0; in < 4; in++) {
            const int col = bn + wn + in * 8 + 2 * tig;
            float2 v0 = make_float2(acc[im][in][0], acc[im][in][1]);
            float2 v1 = make_float2(acc[im][in][2], acc[im][in][3]);
            if (EPI == 3 || EPI == 4) {
                const float2 bb = *(const float2*)&bias[col];
                v0.x += bb.x; v0.y += bb.y;
                v1.x += bb.x; v1.y += bb.y;
            }
            if (EPI == 4) {
                v0.x = fmaxf(v0.x, 0.f); v0.y = fmaxf(v0.y, 0.f);
                v1.x = fmaxf(v1.x, 0.f); v1.y = fmaxf(v1.y, 0.f);
            }
            if (EPI == 1 || EPI == 3) {
                const float2 c0 = *(const float2*)&Cadd[(size_t)r0 * NC + col];
                const float2 c1 = *(const float2*)&Cadd[(size_t)(r0 + 8) * NC + col];
                v0.x += c0.x; v0.y += c0.y;
                v1.x += c1.x; v1.y += c1.y;
            }
            if (EPI == 4) {
                __half* Ch = (__half*)Cout;
                *(uint32_t*)&Ch[(size_t)r0 * NC + col] =
                    h2u(__floats2half2_rn(v0.x, v0.y));
                *(uint32_t*)&Ch[(size_t)(r0 + 8) * NC + col] =
                    h2u(__floats2half2_rn(v1.x, v1.y));
            } else if (EPI == 0 && rkrv) {
                *(uint32_t*)&g_projh[(size_t)r0 * NC + col] =
                    h2u(__floats2half2_rn(v0.x, v0.y));
                *(uint32_t*)&g_projh[(size_t)(r0 + 8) * NC + col] =
                    h2u(__floats2half2_rn(v1.x, v1.y));
            } else {
                float* Cf = (float*)Cout;
                *(float2*)&Cf[(size_t)r0 * NC + col]       = v0;
                *(float2*)&Cf[(size_t)(r0 + 8) * NC + col] = v1;
            }
        }
    }
}

__global__ __launch_bounds__(256, 2) void k_proj_tc()
{ gemm_hh<Dd, DFF, 0>(g_hh, g_Wh_qkv, nullptr, nullptr, g_proj); }

__global__ __launch_bounds__(256, 2) void k_wo_tc()
{ gemm_hh<Dd, Dd, 1>(g_att, g_Wh_o, g_h, nullptr, g_hres); }

__global__ __launch_bounds__(256, 2) void k_ffn1_tc(const float* __restrict__ b1)
{ gemm_hh<Dd, DFF, 4>(g_h2h, g_Wh_1, nullptr, b1, g_ffn); }

__global__ __launch_bounds__(256, 2) void k_ffn2_tc(const float* __restrict__ b2,
                                                    float* __restrict__ out)
{ gemm_hh<DFF, Dd, 3>(g_ffn, g_Wh_2, g_h2, b2, out); }

// ============================================================================
// Triangle attention (attn11): TX=8, 16 y-rows/CTA, 64 threads, 512 CTAs.
// ============================================================================
__global__ __launch_bounds__(64) void attn11_kernel()
{
    const int bx = blockIdx.x;
    const int xt = bx >> 2;
    const int yq = bx & 3;
    const int hh = blockIdx.y;
    const int b  = blockIdx.z;
    const int t  = threadIdx.x;
    const int yl = t >> 2;
    const int dq = t & 3;
    const int x0 = xt * TX;
    const int y0 = yq * 16;
    const int y  = y0 + yl;

    __shared__ __half rk_s[2][16][32];
    __shared__ __half rv_s[2][16][32];
    __shared__ float  lk_s[2][TX][36];
    __shared__ float  lv_s[2][TX][36];

    const int lr  = t >> 2;
    const int lc8 = (t & 3) * 8;
    const int xr  = t >> 3;
    const int lc4 = (t & 7) * 4;

    uint4 prk, prv;
    float4 plk, plv;
    u64 pmN, pmC;

    {
        const size_t baseR = ((size_t)(b * Nn) * Nn + y0 + lr) * DFF + hh * DKk;
        prk = *(const uint4*)&g_projh[baseR + 256 + lc8];
        prv = *(const uint4*)&g_projh[baseR + 768 + lc8];
        const int baseL = ((b * Nn + x0 + xr) * Nn) * DFF + hh * DKk;
        plk = *(const float4*)&g_proj[baseL + lc4];
        plv = *(const float4*)&g_proj[baseL + 512 + lc4];
        pmN = *(const u64*)&g_maskT[((b * Nn) * Nn + y) * 64 + x0];
    }
    *(uint4*)&rk_s[0][lr][lc8] = prk;
    *(uint4*)&rv_s[0][lr][lc8] = prv;
    *(float4*)&lk_s[0][xr][lc4] = plk;
    *(float4*)&lv_s[0][xr][lc4] = plv;
    __syncthreads();

    u64 acc[TX][4];
    float l[TX];
#pragma unroll
    for (int xx = 0; xx < TX; xx++) {
        l[xx] = 0.f;
#pragma unroll
        for (int j = 0; j < 4; j++) acc[xx][j] = 0ull;
    }

    for (int a = 0; a < Nn; a++) {
        const int buf = a & 1;

        pmC = pmN;
        if (a + 1 < Nn) {
            const size_t baseR = ((size_t)(b * Nn + (a + 1)) * Nn + y0 + lr) * DFF + hh * DKk;
            prk = *(const uint4*)&g_projh[baseR + 256 + lc8];
            prv = *(const uint4*)&g_projh[baseR + 768 + lc8];
            const int baseL = ((b * Nn + x0 + xr) * Nn + (a + 1)) * DFF + hh * DKk;
            plk = *(const float4*)&g_proj[baseL + lc4];
            plv = *(const float4*)&g_proj[baseL + 512 + lc4];
            pmN = *(const u64*)&g_maskT[((b * Nn + (a + 1)) * Nn + y) * 64 + x0];
        }

        const uint4 hrk = *(const uint4*)&rk_s[buf][yl][dq * 8];
        const uint4 hrv = *(const uint4*)&rv_s[buf][yl][dq * 8];
        u64 rka0, rka1, rkb0, rkb1, rva0, rva1, rvb0, rvb1;
        h8_to_f32x2(hrk, rka0, rka1, rkb0, rkb1);
        h8_to_f32x2(hrv, rva0, rva1, rvb0, rvb1);

#pragma unroll
        for (int xx = 0; xx < TX; xx++) {
            const ulonglong2 lka = *(const ulonglong2*)&lk_s[buf][xx][dq * 8];
            const ulonglong2 lkb = *(const ulonglong2*)&lk_s[buf][xx][dq * 8 + 4];
            u64 s2 = mul2(lka.x, rka0);
            s2 = fma2(lka.y, rka1, s2);
            s2 = fma2(lkb.x, rkb0, s2);
            s2 = fma2(lkb.y, rkb1, s2);
            float lo, hi;
            upk2(s2, lo, hi);
            float part = lo + hi;
            part += __shfl_xor_sync(0xffffffffu, part, 1);
            part += __shfl_xor_sync(0xffffffffu, part, 2);
            const float sc = ((pmC >> (xx * 8)) & 0xffull) ? -1e9f : part;
            const float p  = __expf(sc);
            l[xx] += p;
            const u64 pp = pk2(p, p);
            const ulonglong2 lva = *(const ulonglong2*)&lv_s[buf][xx][dq * 8];
            const ulonglong2 lvb = *(const ulonglong2*)&lv_s[buf][xx][dq * 8 + 4];
            acc[xx][0] = fma2(mul2(lva.x, rva0), pp, acc[xx][0]);
            acc[xx][1] = fma2(mul2(lva.y, rva1), pp, acc[xx][1]);
            acc[xx][2] = fma2(mul2(lvb.x, rvb0), pp, acc[xx][2]);
            acc[xx][3] = fma2(mul2(lvb.y, rvb1), pp, acc[xx][3]);
        }

        if (a + 1 < Nn) {
            const int nb = buf ^ 1;
            *(uint4*)&rk_s[nb][lr][lc8] = prk;
            *(uint4*)&rv_s[nb][lr][lc8] = prv;
            *(float4*)&lk_s[nb][xr][lc4] = plk;
            *(float4*)&lv_s[nb][xr][lc4] = plv;
            __syncthreads();
        }
    }

#pragma unroll
    for (int xx = 0; xx < TX; xx++) {
        const float inv = 1.0f / l[xx];
        const int ob = ((b * Nn + x0 + xx) * Nn + y) * Dd + hh * DKk + dq * 8;
        float a0, a1, a2, a3, a4, a5, a6, a7;
        upk2(acc[xx][0], a0, a1);
        upk2(acc[xx][1], a2, a3);
        upk2(acc[xx][2], a4, a5);
        upk2(acc[xx][3], a6, a7);
        uint4 hv;
        hv.x = h2u(__floats2half2_rn(a0 * inv, a1 * inv));
        hv.y = h2u(__floats2half2_rn(a2 * inv, a3 * inv));
        hv.z = h2u(__floats2half2_rn(a4 * inv, a5 * inv));
        hv.w = h2u(__floats2half2_rn(a6 * inv, a7 * inv));
        *(uint4*)&g_att[ob] = hv;
    }
}

// ============================================================================
// launch
// ============================================================================
extern "C" void kernel_launch(void* const* d_in, const int* in_sizes, int n_in,
                              void* d_out, int out_size)
{
    const float*         x    = (const float*)d_in[0];
    const unsigned char* mask = (const unsigned char*)d_in[1];
    const float*         Wlk  = (const float*)d_in[2];
    const float*         Wrk  = (const float*)d_in[3];
    const float*         Wlv  = (const float*)d_in[4];
    const float*         Wrv  = (const float*)d_in[5];
    const float*         Wo   = (const float*)d_in[6];
    const float*         W1   = (const float*)d_in[7];
    const float*         b1   = (const float*)d_in[8];
    const float*         W2   = (const float*)d_in[9];
    const float*         b2   = (const float*)d_in[10];
    const float*         g1   = (const float*)d_in[11];
    const float*         be1  = (const float*)d_in[12];
    const float*         g2   = (const float*)d_in[13];
    const float*         be2  = (const float*)d_in[14];
    float* out = (float*)d_out;

    // >48KB dynamic smem opt-in (idempotent; passed graph capture in round 6)
    cudaFuncSetAttribute(k_proj_tc, cudaFuncAttributeMaxDynamicSharedMemorySize, DSMEM);
    cudaFuncSetAttribute(k_wo_tc,   cudaFuncAttributeMaxDynamicSharedMemorySize, DSMEM);
    cudaFuncSetAttribute(k_ffn1_tc, cudaFuncAttributeMaxDynamicSharedMemorySize, DSMEM);
    cudaFuncSetAttribute(k_ffn2_tc, cudaFuncAttributeMaxDynamicSharedMemorySize, DSMEM);

    k_prep_ln1<<<2880 + RR / 8, 256>>>(Wlk, Wrk, Wlv, Wrv, Wo, W1, W2, mask,
                                       x, g1, be1);
    k_proj_tc<<<dim3(DFF / 128, RR / 128), 256, DSMEM>>>();
    attn11_kernel<<<dim3(32, Hh, Bb), 64>>>();
    k_wo_tc<<<dim3(Dd / 128, RR / 128), 256, DSMEM>>>();
    ln2_kernel<<<RR / 8, 256>>>(g2, be2);
    k_ffn1_tc<<<dim3(DFF / 128, RR / 128), 256, DSMEM>>>(b1);
    k_ffn2_tc<<<dim3(Dd / 128, RR / 128), 256, DSMEM>>>(b2, out);
}

// round 17
// speedup vs baseline: 1.1484x; 1.0004x over previous
#include <cuda_runtime.h>
#include <cuda_fp16.h>
#include <cstdint>

// ============================================================================
// EdgeTransformerLayer (B=2, N=64, D=256, H=8, DK=32, DFF=1024)
// GEMMs: mma.sync.m16n8k16 fp16, 128x128 tiles, cp.async 3-stage pipeline.
// proj: single fp16 output (g_projh); attention streams all operands fp16,
// converts lk/lv to fp32 in the loader (inner loop unchanged).
// Attention: attn11 (TX=8, 16 y-rows/CTA, 64 thr, 512 CTAs).
// ============================================================================

namespace {
constexpr int Bb  = 2;
constexpr int Nn  = 64;
constexpr int Dd  = 256;
constexpr int Hh  = 8;
constexpr int DKk = 32;
constexpr int DFF = 1024;
constexpr int RR  = Bb * Nn * Nn;   // 8192
constexpr int SPH = 40;             // GEMM smem row stride (halfs) = 80B
constexpr int BUFH = 128 * SPH;
constexpr int DSMEM = 3 * 2 * BUFH * 2;  // 61440 B
constexpr int TX  = 8;
}

// ---- device-global scratch ---------------------------------------------------
__device__ float  g_h     [RR * Dd];
__device__ __half g_hh    [RR * Dd];
__device__ __half g_projh [RR * DFF];  // fp16: [0,256)=lk*scale [256,512)=rk [512,768)=lv [768,1024)=rv
__device__ __half g_att   [RR * Dd];
__device__ float  g_hres  [RR * Dd];
__device__ float  g_h2    [RR * Dd];
__device__ __half g_h2h   [RR * Dd];
__device__ __half g_ffn   [RR * DFF];
__device__ __half g_Wh_qkv[DFF * Dd];
__device__ __half g_Wh_o  [Dd * Dd];
__device__ __half g_Wh_1  [DFF * Dd];
__device__ __half g_Wh_2  [Dd * DFF];
__device__ unsigned char g_maskT[Bb * Nn * Nn * Nn];  // [b][a][y][x]

// ============================================================================
// helpers
// ============================================================================
__device__ __forceinline__ uint32_t smem_u32(const void* p) {
    uint32_t a;
    asm("{ .reg .u64 t; cvta.to.shared.u64 t, %1; cvt.u32.u64 %0, t; }" : "=r"(a) : "l"(p));
    return a;
}

__device__ __forceinline__ void mma_f16(float c[4],
                                        uint32_t a0, uint32_t a1, uint32_t a2, uint32_t a3,
                                        uint32_t b0, uint32_t b1) {
    asm volatile(
        "mma.sync.aligned.m16n8k16.row.col.f32.f16.f16.f32 "
        "{%0,%1,%2,%3}, {%4,%5,%6,%7}, {%8,%9}, {%0,%1,%2,%3};"
        : "+f"(c[0]), "+f"(c[1]), "+f"(c[2]), "+f"(c[3])
        : "r"(a0), "r"(a1), "r"(a2), "r"(a3), "r"(b0), "r"(b1));
}

__device__ __forceinline__ void ldsm_x4(uint32_t r[4], uint32_t addr) {
    asm volatile("ldmatrix.sync.aligned.m8n8.x4.shared.b16 {%0,%1,%2,%3}, [%4];"
                 : "=r"(r[0]), "=r"(r[1]), "=r"(r[2]), "=r"(r[3]) : "r"(addr));
}
__device__ __forceinline__ void ldsm_x2(uint32_t r[2], uint32_t addr) {
    asm volatile("ldmatrix.sync.aligned.m8n8.x2.shared.b16 {%0,%1}, [%2];"
                 : "=r"(r[0]), "=r"(r[1]) : "r"(addr));
}

__device__ __forceinline__ uint32_t h2u(__half2 h) {
    uint32_t u; asm("mov.b32 %0, %1;" : "=r"(u) : "r"(*(uint32_t*)&h)); return u;
}

// cp.async
__device__ __forceinline__ void cp16(uint32_t dst, const void* src) {
    asm volatile("cp.async.cg.shared.global [%0], [%1], 16;"
                 :: "r"(dst), "l"(src) : "memory");
}
#define CP_COMMIT() asm volatile("cp.async.commit_group;" ::: "memory")
#define CP_WAIT1()  asm volatile("cp.async.wait_group 1;" ::: "memory")
#define CP_WAIT0()  asm volatile("cp.async.wait_group 0;" ::: "memory")

typedef unsigned long long u64;
__device__ __forceinline__ u64 pk2(float lo, float hi) {
    u64 r; asm("mov.b64 %0, {%1,%2};" : "=l"(r) : "f"(lo), "f"(hi)); return r;
}
__device__ __forceinline__ void upk2(u64 v, float& lo, float& hi) {
    asm("mov.b64 {%0,%1}, %2;" : "=f"(lo), "=f"(hi) : "l"(v));
}
__device__ __forceinline__ u64 mul2(u64 a, u64 b) {
    u64 d; asm("mul.rn.f32x2 %0, %1, %2;" : "=l"(d) : "l"(a), "l"(b)); return d;
}
__device__ __forceinline__ u64 fma2(u64 a, u64 b, u64 c) {
    u64 d; asm("fma.rn.f32x2 %0, %1, %2, %3;" : "=l"(d) : "l"(a), "l"(b), "l"(c)); return d;
}

__device__ __forceinline__ void h8_to_f32x2(uint4 h, u64& a0, u64& a1, u64& b0, u64& b1) {
    const float2 f0 = __half22float2(*(__half2*)&h.x);
    const float2 f1 = __half22float2(*(__half2*)&h.y);
    const float2 f2 = __half22float2(*(__half2*)&h.z);
    const float2 f3 = __half22float2(*(__half2*)&h.w);
    a0 = pk2(f0.x, f0.y); a1 = pk2(f1.x, f1.y);
    b0 = pk2(f2.x, f2.y); b1 = pk2(f3.x, f3.y);
}

__device__ __forceinline__ void h8_to_2float4(uint4 h, float4& lo, float4& hi) {
    const float2 f0 = __half22float2(*(__half2*)&h.x);
    const float2 f1 = __half22float2(*(__half2*)&h.y);
    const float2 f2 = __half22float2(*(__half2*)&h.z);
    const float2 f3 = __half22float2(*(__half2*)&h.w);
    lo = make_float4(f0.x, f0.y, f1.x, f1.y);
    hi = make_float4(f2.x, f2.y, f3.x, f3.y);
}

// ============================================================================
// LayerNorm body (warp per row)
// ============================================================================
__device__ __forceinline__ void ln_rows(const float* __restrict__ in,
                                        const float* __restrict__ gam,
                                        const float* __restrict__ bet,
                                        float* __restrict__ out,
                                        __half* __restrict__ outh,
                                        int rowBase)
{
    const int row  = rowBase + (threadIdx.x >> 5);
    const int lane = threadIdx.x & 31;
    const float* rp = in + (size_t)row * Dd + lane * 8;
    const float4 v0 = *(const float4*)rp;
    const float4 v1 = *(const float4*)(rp + 4);
    float s  = v0.x + v0.y + v0.z + v0.w + v1.x + v1.y + v1.z + v1.w;
    float s2 = v0.x*v0.x + v0.y*v0.y + v0.z*v0.z + v0.w*v0.w
             + v1.x*v1.x + v1.y*v1.y + v1.z*v1.z + v1.w*v1.w;
#pragma unroll
    for (int o = 16; o; o >>= 1) {
        s  += __shfl_xor_sync(0xffffffffu, s,  o);
        s2 += __shfl_xor_sync(0xffffffffu, s2, o);
    }
    const float mean = s * (1.0f / Dd);
    const float var  = s2 * (1.0f / Dd) - mean * mean;
    const float inv  = rsqrtf(var + 1e-5f);
    const float4 g0 = *(const float4*)(gam + lane * 8);
    const float4 g1 = *(const float4*)(gam + lane * 8 + 4);
    const float4 b0 = *(const float4*)(bet + lane * 8);
    const float4 b1 = *(const float4*)(bet + lane * 8 + 4);
    float4 o0, o1;
    o0.x = (v0.x - mean) * inv * g0.x + b0.x;
    o0.y = (v0.y - mean) * inv * g0.y + b0.y;
    o0.z = (v0.z - mean) * inv * g0.z + b0.z;
    o0.w = (v0.w - mean) * inv * g0.w + b0.w;
    o1.x = (v1.x - mean) * inv * g1.x + b1.x;
    o1.y = (v1.y - mean) * inv * g1.y + b1.y;
    o1.z = (v1.z - mean) * inv * g1.z + b1.z;
    o1.w = (v1.w - mean) * inv * g1.w + b1.w;
    float* op = out + (size_t)row * Dd + lane * 8;
    *(float4*)op       = o0;
    *(float4*)(op + 4) = o1;
    uint4 hv;
    hv.x = h2u(__floats2half2_rn(o0.x, o0.y));
    hv.y = h2u(__floats2half2_rn(o0.z, o0.w));
    hv.z = h2u(__floats2half2_rn(o1.x, o1.y));
    hv.w = h2u(__floats2half2_rn(o1.z, o1.w));
    *(uint4*)(outh + (size_t)row * Dd + lane * 8) = hv;
}

// ============================================================================
// fused prep + ln1
// ============================================================================
__device__ __forceinline__ __half* trh_dst(int which) {
    switch (which) {
        case 0: return g_Wh_qkv;
        case 1: return g_Wh_qkv + 256 * 256;
        case 2: return g_Wh_qkv + 512 * 256;
        case 3: return g_Wh_qkv + 768 * 256;
        case 4: return g_Wh_o;
        case 5: return g_Wh_1;
        default: return g_Wh_2;
    }
}

__global__ __launch_bounds__(256) void k_prep_ln1(const float* __restrict__ Wlk,
                                                  const float* __restrict__ Wrk,
                                                  const float* __restrict__ Wlv,
                                                  const float* __restrict__ Wrv,
                                                  const float* __restrict__ Wo,
                                                  const float* __restrict__ W1,
                                                  const float* __restrict__ W2,
                                                  const unsigned char* __restrict__ mask,
                                                  const float* __restrict__ x,
                                                  const float* __restrict__ g1,
                                                  const float* __restrict__ be1)
{
    const int id = blockIdx.x;
    if (id >= 2880) {
        ln_rows(x, g1, be1, g_h, g_hh, (id - 2880) * 8);
        return;
    }
    if (id >= 832) {
        const int g = (id - 832) * 256 + threadIdx.x;
        const int xx = g & 63;
        const int yy = (g >> 6) & 63;
        const int a  = (g >> 12) & 63;
        const int bb = g >> 18;
        g_maskT[g] = mask[(((bb * 64 + xx) * 64 + a) * 64) + yy];
        return;
    }

    __shared__ float tile[32][33];
    const float* src;
    __half* dst;
    float scale = 1.0f;
    int K, N, n0, k0;
    if (id < 320) {
        const int w = id >> 6;
        const int tl = id & 63;
        src = (w == 0) ? Wlk : (w == 1) ? Wrk : (w == 2) ? Wlv : (w == 3) ? Wrv : Wo;
        dst = trh_dst(w);
        if (w == 0) scale = 0.17677669529663687f;   // 1/sqrt(32)
        K = 256; N = 256;
        n0 = (tl & 7) * 32; k0 = (tl >> 3) * 32;
    } else if (id < 576) {
        const int tl = id - 320;
        src = W1; dst = g_Wh_1; K = 256; N = 1024;
        n0 = (tl & 31) * 32; k0 = (tl >> 5) * 32;
    } else {
        const int tl = id - 576;
        src = W2; dst = g_Wh_2; K = 1024; N = 256;
        n0 = (tl & 7) * 32; k0 = (tl >> 3) * 32;
    }
    const int tx = threadIdx.x & 31;
    const int ty = threadIdx.x >> 5;
#pragma unroll
    for (int r = ty; r < 32; r += 8)
        tile[r][tx] = src[(size_t)(k0 + r) * N + n0 + tx];
    __syncthreads();
#pragma unroll
    for (int r = ty; r < 32; r += 8)
        dst[(size_t)(n0 + r) * K + k0 + tx] = __float2half_rn(tile[tx][r] * scale);
}

__global__ __launch_bounds__(256) void ln2_kernel(const float* __restrict__ g2,
                                                  const float* __restrict__ be2)
{ ln_rows(g_hres, g2, be2, g_h2, g_h2h, blockIdx.x * 8); }

// ============================================================================
// fp16 mma GEMM, 128x128 CTA tile, cp.async 3-stage pipeline.
// EPI: 0 proj -> fp16 (g_projh); 1 +Cadd f32; 3 +bias+Cadd f32;
//      4 +bias,relu -> fp16.
// ============================================================================
template <int K, int NC, int EPI>
__device__ __forceinline__ void gemm_hh(const __half* __restrict__ A,
                                        const __half* __restrict__ Wh,
                                        const float* __restrict__ Cadd,
                                        const float* __restrict__ bias,
                                        void* __restrict__ Cout)
{
    constexpr int NCH = K / 32;
    extern __shared__ __half dsm[];
    __half* As = dsm;
    __half* Bs = dsm + 3 * BUFH;
    constexpr uint32_t STB = BUFH * 2;

    const int t    = threadIdx.x;
    const int lane = t & 31;
    const int wid  = t >> 5;
    const int gr   = lane >> 2;
    const int tig  = lane & 3;
    const int wm   = (wid & 1) * 64;
    const int wn   = (wid >> 1) * 32;

    const int bm = blockIdx.y * 128;
    const int bn = blockIdx.x * 128;

    const uint32_t as0 = smem_u32(As);
    const uint32_t bs0 = smem_u32(Bs);
    const uint32_t a_base = as0 + ((wm + (lane & 15)) * SPH + ((lane >> 4) & 1) * 8) * 2;
    const uint32_t b_base = bs0 + ((wn + (lane & 7)) * SPH + ((lane >> 3) & 1) * 8) * 2;

    const int lrow = t >> 1;
    const int lko  = (t & 1) * 16;
    const __half* Ag = A  + (size_t)(bm + lrow) * K + lko;
    const __half* Bg = Wh + (size_t)(bn + lrow) * K + lko;
    const uint32_t aws = as0 + (uint32_t)((lrow * SPH + lko) * 2);
    const uint32_t bws = bs0 + (uint32_t)((lrow * SPH + lko) * 2);

    float acc[4][4][4];
#pragma unroll
    for (int im = 0; im < 4; im++)
#pragma unroll
        for (int in = 0; in < 4; in++)
#pragma unroll
            for (int j = 0; j < 4; j++) acc[im][in][j] = 0.f;

#pragma unroll
    for (int c = 0; c < 2; c++) {
        const uint32_t so = (uint32_t)(c % 3) * STB;
        cp16(aws + so,      Ag + c * 32);
        cp16(aws + so + 16, Ag + c * 32 + 8);
        cp16(bws + so,      Bg + c * 32);
        cp16(bws + so + 16, Bg + c * 32 + 8);
        CP_COMMIT();
    }

    for (int c = 0; c < NCH; c++) {
        if (c == NCH - 1) CP_WAIT0(); else CP_WAIT1();
        __syncthreads();

        if (c + 2 < NCH) {
            const uint32_t so = (uint32_t)((c + 2) % 3) * STB;
            cp16(aws + so,      Ag + (c + 2) * 32);
            cp16(aws + so + 16, Ag + (c + 2) * 32 + 8);
            cp16(bws + so,      Bg + (c + 2) * 32);
            cp16(bws + so + 16, Bg + (c + 2) * 32 + 8);
            CP_COMMIT();
        }

        const uint32_t so = (uint32_t)(c % 3) * STB;
        const uint32_t a_addr = a_base + so;
        const uint32_t b_addr = b_base + so;
#pragma unroll
        for (int ks = 0; ks < 2; ks++) {
            uint32_t af[4][4], bf[4][2];
#pragma unroll
            for (int im = 0; im < 4; im++)
                ldsm_x4(af[im], a_addr + (uint32_t)(im * 16 * SPH * 2 + ks * 32));
#pragma unroll
            for (int in = 0; in < 4; in++)
                ldsm_x2(bf[in], b_addr + (uint32_t)(in * 8 * SPH * 2 + ks * 32));
#pragma unroll
            for (int im = 0; im < 4; im++)
#pragma unroll
                for (int in = 0; in < 4; in++)
                    mma_f16(acc[im][in], af[im][0], af[im][1], af[im][2], af[im][3],
                            bf[in][0], bf[in][1]);
        }
    }

    // epilogue
#pragma unroll
    for (int im = 0; im < 4; im++) {
        const int r0 = bm + wm + im * 16 + gr;
#pragma unroll
        for (int in = 0; in < 4; in++) {
            const int col = bn + wn + in * 8 + 2 * tig;
            float2 v0 = make_float2(acc[im][in][0], acc[im][in][1]);
            float2 v1 = make_float2(acc[im][in][2], acc[im][in][3]);
            if (EPI == 3 || EPI == 4) {
                const float2 bb = *(const float2*)&bias[col];
                v0.x += bb.x; v0.y += bb.y;
                v1.x += bb.x; v1.y += bb.y;
            }
            if (EPI == 4) {
                v0.x = fmaxf(v0.x, 0.f); v0.y = fmaxf(v0.y, 0.f);
                v1.x = fmaxf(v1.x, 0.f); v1.y = fmaxf(v1.y, 0.f);
            }
            if (EPI == 1 || EPI == 3) {
                const float2 c0 = *(const float2*)&Cadd[(size_t)r0 * NC + col];
                const float2 c1 = *(const float2*)&Cadd[(size_t)(r0 + 8) * NC + col];
                v0.x += c0.x; v0.y += c0.y;
                v1.x += c1.x; v1.y += c1.y;
            }
            if (EPI == 4 || EPI == 0) {
                __half* Ch = (EPI == 0) ? g_projh : (__half*)Cout;
                *(uint32_t*)&Ch[(size_t)r0 * NC + col] =
                    h2u(__floats2half2_rn(v0.x, v0.y));
                *(uint32_t*)&Ch[(size_t)(r0 + 8) * NC + col] =
                    h2u(__floats2half2_rn(v1.x, v1.y));
            } else {
                float* Cf = (float*)Cout;
                *(float2*)&Cf[(size_t)r0 * NC + col]       = v0;
                *(float2*)&Cf[(size_t)(r0 + 8) * NC + col] = v1;
            }
        }
    }
}

__global__ __launch_bounds__(256, 2) void k_proj_tc()
{ gemm_hh<Dd, DFF, 0>(g_hh, g_Wh_qkv, nullptr, nullptr, nullptr); }

__global__ __launch_bounds__(256, 2) void k_wo_tc()
{ gemm_hh<Dd, Dd, 1>(g_att, g_Wh_o, g_h, nullptr, g_hres); }

__global__ __launch_bounds__(256, 2) void k_ffn1_tc(const float* __restrict__ b1)
{ gemm_hh<Dd, DFF, 4>(g_h2h, g_Wh_1, nullptr, b1, g_ffn); }

__global__ __launch_bounds__(256, 2) void k_ffn2_tc(const float* __restrict__ b2,
                                                    float* __restrict__ out)
{ gemm_hh<DFF, Dd, 3>(g_ffn, g_Wh_2, g_h2, b2, out); }

// ============================================================================
// Triangle attention (attn12): TX=8, 16 y-rows/CTA, 64 threads, 512 CTAs.
// ALL streams fp16 from g_projh; lk/lv converted fp16->fp32 in the loader
// (t<32, 16 cvt each); inner loop identical to attn11.
// ============================================================================
__global__ __launch_bounds__(64) void attn12_kernel()
{
    const int bx = blockIdx.x;
    const int xt = bx >> 2;
    const int yq = bx & 3;
    const int hh = blockIdx.y;
    const int b  = blockIdx.z;
    const int t  = threadIdx.x;
    const int yl = t >> 2;
    const int dq = t & 3;
    const int x0 = xt * TX;
    const int y0 = yq * 16;
    const int y  = y0 + yl;

    __shared__ __half rk_s[2][16][32];
    __shared__ __half rv_s[2][16][32];
    __shared__ float  lk_s[2][TX][36];
    __shared__ float  lv_s[2][TX][36];

    const int lr  = t >> 2;          // rk/rv row 0..15
    const int lc8 = (t & 3) * 8;
    const int xr  = t >> 2;          // lk/lv row 0..7 (t<32)
    const int xc8 = (t & 3) * 8;     // 8-half column offset

    uint4 prk, prv, plk, plv;
    u64 pmN, pmC;

    {
        const size_t baseR = ((size_t)(b * Nn) * Nn + y0 + lr) * DFF + hh * DKk;
        prk = *(const uint4*)&g_projh[baseR + 256 + lc8];
        prv = *(const uint4*)&g_projh[baseR + 768 + lc8];
        if (t < 32) {
            const size_t baseL = ((size_t)(b * Nn + x0 + xr) * Nn) * DFF + hh * DKk;
            plk = *(const uint4*)&g_projh[baseL + xc8];
            plv = *(const uint4*)&g_projh[baseL + 512 + xc8];
        }
        pmN = *(const u64*)&g_maskT[((b * Nn) * Nn + y) * 64 + x0];
    }
    *(uint4*)&rk_s[0][lr][lc8] = prk;
    *(uint4*)&rv_s[0][lr][lc8] = prv;
    if (t < 32) {
        float4 lo, hi;
        h8_to_2float4(plk, lo, hi);
        *(float4*)&lk_s[0][xr][xc8]     = lo;
        *(float4*)&lk_s[0][xr][xc8 + 4] = hi;
        h8_to_2float4(plv, lo, hi);
        *(float4*)&lv_s[0][xr][xc8]     = lo;
        *(float4*)&lv_s[0][xr][xc8 + 4] = hi;
    }
    __syncthreads();

    u64 acc[TX][4];
    float l[TX];
#pragma unroll
    for (int xx = 0; xx < TX; xx++) {
        l[xx] = 0.f;
#pragma unroll
        for (int j = 0; j < 4; j++) acc[xx][j] = 0ull;
    }

    for (int a = 0; a < Nn; a++) {
        const int buf = a & 1;

        pmC = pmN;
        if (a + 1 < Nn) {
            const size_t baseR = ((size_t)(b * Nn + (a + 1)) * Nn + y0 + lr) * DFF + hh * DKk;
            prk = *(const uint4*)&g_projh[baseR + 256 + lc8];
            prv = *(const uint4*)&g_projh[baseR + 768 + lc8];
            if (t < 32) {
                const size_t baseL = ((size_t)(b * Nn + x0 + xr) * Nn + (a + 1)) * DFF + hh * DKk;
                plk = *(const uint4*)&g_projh[baseL + xc8];
                plv = *(const uint4*)&g_projh[baseL + 512 + xc8];
            }
            pmN = *(const u64*)&g_maskT[((b * Nn + (a + 1)) * Nn + y) * 64 + x0];
        }

        const uint4 hrk = *(const uint4*)&rk_s[buf][yl][dq * 8];
        const uint4 hrv = *(const uint4*)&rv_s[buf][yl][dq * 8];
        u64 rka0, rka1, rkb0, rkb1, rva0, rva1, rvb0, rvb1;
        h8_to_f32x2(hrk, rka0, rka1, rkb0, rkb1);
        h8_to_f32x2(hrv, rva0, rva1, rvb0, rvb1);

#pragma unroll
        for (int xx = 0; xx < TX; xx++) {
            const ulonglong2 lka = *(const ulonglong2*)&lk_s[buf][xx][dq * 8];
            const ulonglong2 lkb = *(const ulonglong2*)&lk_s[buf][xx][dq * 8 + 4];
            u64 s2 = mul2(lka.x, rka0);
            s2 = fma2(lka.y, rka1, s2);
            s2 = fma2(lkb.x, rkb0, s2);
            s2 = fma2(lkb.y, rkb1, s2);
            float lo, hi;
            upk2(s2, lo, hi);
            float part = lo + hi;
            part += __shfl_xor_sync(0xffffffffu, part, 1);
            part += __shfl_xor_sync(0xffffffffu, part, 2);
            const float sc = ((pmC >> (xx * 8)) & 0xffull) ? -1e9f : part;
            const float p  = __expf(sc);
            l[xx] += p;
            const u64 pp = pk2(p, p);
            const ulonglong2 lva = *(const ulonglong2*)&lv_s[buf][xx][dq * 8];
            const ulonglong2 lvb = *(const ulonglong2*)&lv_s[buf][xx][dq * 8 + 4];
            acc[xx][0] = fma2(mul2(lva.x, rva0), pp, acc[xx][0]);
            acc[xx][1] = fma2(mul2(lva.y, rva1), pp, acc[xx][1]);
            acc[xx][2] = fma2(mul2(lvb.x, rvb0), pp, acc[xx][2]);
            acc[xx][3] = fma2(mul2(lvb.y, rvb1), pp, acc[xx][3]);
        }

        if (a + 1 < Nn) {
            const int nb = buf ^ 1;
            *(uint4*)&rk_s[nb][lr][lc8] = prk;
            *(uint4*)&rv_s[nb][lr][lc8] = prv;
            if (t < 32) {
                float4 lo, hi;
                h8_to_2float4(plk, lo, hi);
                *(float4*)&lk_s[nb][xr][xc8]     = lo;
                *(float4*)&lk_s[nb][xr][xc8 + 4] = hi;
                h8_to_2float4(plv, lo, hi);
                *(float4*)&lv_s[nb][xr][xc8]     = lo;
                *(float4*)&lv_s[nb][xr][xc8 + 4] = hi;
            }
            __syncthreads();
        }
    }

#pragma unroll
    for (int xx = 0; xx < TX; xx++) {
        const float inv = 1.0f / l[xx];
        const int ob = ((b * Nn + x0 + xx) * Nn + y) * Dd + hh * DKk + dq * 8;
        float a0, a1, a2, a3, a4, a5, a6, a7;
        upk2(acc[xx][0], a0, a1);
        upk2(acc[xx][1], a2, a3);
        upk2(acc[xx][2], a4, a5);
        upk2(acc[xx][3], a6, a7);
        uint4 hv;
        hv.x = h2u(__floats2half2_rn(a0 * inv, a1 * inv));
        hv.y = h2u(__floats2half2_rn(a2 * inv, a3 * inv));
        hv.z = h2u(__floats2half2_rn(a4 * inv, a5 * inv));
        hv.w = h2u(__floats2half2_rn(a6 * inv, a7 * inv));
        *(uint4*)&g_att[ob] = hv;
    }
}

// ============================================================================
// launch
// ============================================================================
extern "C" void kernel_launch(void* const* d_in, const int* in_sizes, int n_in,
                              void* d_out, int out_size)
{
    const float*         x    = (const float*)d_in[0];
    const unsigned char* mask = (const unsigned char*)d_in[1];
    const float*         Wlk  = (const float*)d_in[2];
    const float*         Wrk  = (const float*)d_in[3];
    const float*         Wlv  = (const float*)d_in[4];
    const float*         Wrv  = (const float*)d_in[5];
    const float*         Wo   = (const float*)d_in[6];
    const float*         W1   = (const float*)d_in[7];
    const float*         b1   = (const float*)d_in[8];
    const float*         W2   = (const float*)d_in[9];
    const float*         b2   = (const float*)d_in[10];
    const float*         g1   = (const float*)d_in[11];
    const float*         be1  = (const float*)d_in[12];
    const float*         g2   = (const float*)d_in[13];
    const float*         be2  = (const float*)d_in[14];
    float* out = (float*)d_out;

    cudaFuncSetAttribute(k_proj_tc, cudaFuncAttributeMaxDynamicSharedMemorySize, DSMEM);
    cudaFuncSetAttribute(k_wo_tc,   cudaFuncAttributeMaxDynamicSharedMemorySize, DSMEM);
    cudaFuncSetAttribute(k_ffn1_tc, cudaFuncAttributeMaxDynamicSharedMemorySize, DSMEM);
    cudaFuncSetAttribute(k_ffn2_tc, cudaFuncAttributeMaxDynamicSharedMemorySize, DSMEM);

    k_prep_ln1<<<2880 + RR / 8, 256>>>(Wlk, Wrk, Wlv, Wrv, Wo, W1, W2, mask,
                                       x, g1, be1);
    k_proj_tc<<<dim3(DFF / 128, RR / 128), 256, DSMEM>>>();
    attn12_kernel<<<dim3(32, Hh, Bb), 64>>>();
    k_wo_tc<<<dim3(Dd / 128, RR / 128), 256, DSMEM>>>();
    ln2_kernel<<<RR / 8, 256>>>(g2, be2);
    k_ffn1_tc<<<dim3(DFF / 128, RR / 128), 256, DSMEM>>>(b1);
    k_ffn2_tc<<<dim3(Dd / 128, RR / 128), 256, DSMEM>>>(b2, out);
}